// round 1
// baseline (speedup 1.0000x reference)
#include <cuda_runtime.h>
#include <cstdint>

// ---------------------------------------------------------------------------
// CVAE forward: encoder 3xLSTM -> reparam -> decoder 3xLSTM -> CE + KL
// B=256 T=128 U=512 LAT=200 V=42 P=3
// Round 1: fp32 baseline. Persistent recurrent kernel, 128 CTAs, global
// spin barrier per time step, h double-buffered through L2 (__ldcg/__stcg).
// ---------------------------------------------------------------------------

constexpr int cB = 256, cT = 128, cU = 512, cLAT = 200, cV = 42, cP = 3;
constexpr int G4U = 2048;              // 4*U
constexpr int NB = 32, NU = 32;        // per-CTA tile: 32 batch x 32 hidden
constexpr int NCTA = 128, NTHR = 256;

// ------------------------------- scratch -----------------------------------
__device__ float g_seqA[cB * cT * cU];       // 64 MB
__device__ float g_seqB[cB * cT * cU];       // 64 MB
__device__ float g_h[2][cB * cU];            // h double buffer
__device__ float g_c[cB * cU];               // final cell state of a pass
__device__ float g_Eenc[cV * G4U];           // emb_enc @ enc_k0[:200]
__device__ float g_Edec[cV * G4U];           // emb_dec @ dec_k0[200:400]
__device__ float g_CbEnc[cB * G4U];          // C @ enc_k0[200:203] + enc_b0
__device__ float g_CbDec[cB * G4U];          // C @ dec_k0[400:403] + dec_b0
__device__ float g_Cz[cB * G4U];             // g_CbDec + z @ dec_k0[:200]
__device__ float g_z[cB * cLAT];
__device__ float g_latpart[cB];
__device__ float g_reconpart[512];
__device__ unsigned g_bar[8];

// ------------------------------ grid barrier -------------------------------
__device__ __forceinline__ void grid_bar(unsigned* ctr, unsigned target) {
    __threadfence();
    __syncthreads();
    if (threadIdx.x == 0) {
        atomicAdd(ctr, 1u);
        while (*(volatile unsigned*)ctr < target) __nanosleep(64);
        __threadfence();
    }
    __syncthreads();
}

// ------------------------------ prep kernel --------------------------------
// blocks 0..41: E_enc row v; 42..83: E_dec row v; 84..339: CbEnc row b;
// 340..595: CbDec row b; 596..603: zero h buffers; 604: zero barriers.
__global__ void prep_kernel(const float* __restrict__ emb_enc,
                            const float* __restrict__ emb_dec,
                            const float* __restrict__ enc_k0,
                            const float* __restrict__ dec_k0,
                            const float* __restrict__ enc_b0,
                            const float* __restrict__ dec_b0,
                            const float* __restrict__ Cmat) {
    const int bid = blockIdx.x, tid = threadIdx.x;
    if (bid < 42) {
        const int v = bid;
        for (int n = tid; n < G4U; n += NTHR) {
            float acc = 0.f;
            for (int l = 0; l < cLAT; l++)
                acc += emb_enc[v * cLAT + l] * enc_k0[l * G4U + n];
            g_Eenc[v * G4U + n] = acc;
        }
    } else if (bid < 84) {
        const int v = bid - 42;
        for (int n = tid; n < G4U; n += NTHR) {
            float acc = 0.f;
            for (int l = 0; l < cLAT; l++)
                acc += emb_dec[v * cLAT + l] * dec_k0[(cLAT + l) * G4U + n];
            g_Edec[v * G4U + n] = acc;
        }
    } else if (bid < 340) {
        const int b = bid - 84;
        for (int n = tid; n < G4U; n += NTHR) {
            float acc = enc_b0[n];
            for (int p = 0; p < cP; p++)
                acc += Cmat[b * cP + p] * enc_k0[(cLAT + p) * G4U + n];
            g_CbEnc[b * G4U + n] = acc;
        }
    } else if (bid < 596) {
        const int b = bid - 340;
        for (int n = tid; n < G4U; n += NTHR) {
            float acc = dec_b0[n];
            for (int p = 0; p < cP; p++)
                acc += Cmat[b * cP + p] * dec_k0[(2 * cLAT + p) * G4U + n];
            g_CbDec[b * G4U + n] = acc;
        }
    } else if (bid < 604) {
        const int base = (bid - 596) * 32768;
        float* hflat = &g_h[0][0];
        for (int i = tid; i < 32768; i += NTHR) hflat[base + i] = 0.f;
    } else {
        if (tid < 8) g_bar[tid] = 0u;
    }
}

// --------------------------- recurrent LSTM pass ---------------------------
// KX = 0 : layer 0 variant — input projection comes from E-table gather + Cb.
// KX = 512: layers 1/2 — z = [x_t ; h] @ [Wk ; Wr], K = 1024.
// Grid: 128 CTAs = 8 batch tiles x 16 hidden tiles. 256 threads.
template <int KX>
__global__ void rec_kernel(const float* __restrict__ Wk,
                           const float* __restrict__ Wr,
                           const float* __restrict__ bias,
                           const int* __restrict__ Xidx,
                           int sel_in, int sel_out, int sel_dec, int pass_id) {
    constexpr int KA = KX + 512;
    extern __shared__ float sm[];
    float* As  = sm;                 // [NB][KA]
    float* Wsh = sm + NB * KA;       // [32][128]

    const float* seq_in  = sel_in  ? g_seqB : g_seqA;
    float*       seq_out = sel_out ? g_seqB : g_seqA;
    const float* Etab = sel_dec ? g_Edec : g_Eenc;
    const float* Cb   = sel_dec ? g_Cz   : g_CbEnc;

    const int tid = threadIdx.x;
    const int u   = tid & 31;        // lane = hidden col within tile
    const int bg  = tid >> 5;        // warp id -> 4 batch rows
    const int b0  = (blockIdx.x >> 4) * NB;
    const int u0  = (blockIdx.x & 15) * NU;

    // zero my slice of both h buffers
    for (int i = tid; i < NB * NU; i += NTHR) {
        const int bb = i >> 5, uu = i & 31;
        g_h[0][(b0 + bb) * cU + u0 + uu] = 0.f;
        g_h[1][(b0 + bb) * cU + u0 + uu] = 0.f;
    }
    unsigned nbar = 0;
    grid_bar(&g_bar[pass_id], (++nbar) * NCTA);

    float creg[4] = {0.f, 0.f, 0.f, 0.f};

    for (int t = 0; t < cT; t++) {
        const float* hcur = g_h[t & 1];
        float*       hnxt = g_h[(t & 1) ^ 1];

        // stage A = [x_t ; h]
        if (KX > 0) {
            for (int i = tid; i < NB * 512; i += NTHR) {
                const int r = i >> 9, c = i & 511;
                As[r * KA + c] = seq_in[((b0 + r) * cT + t) * cU + c];
            }
        }
        for (int i = tid; i < NB * 512; i += NTHR) {
            const int r = i >> 9, c = i & 511;
            As[r * KA + KX + c] = __ldcg(&hcur[(b0 + r) * cU + c]);
        }
        __syncthreads();

        float acc[4][4];
#pragma unroll
        for (int j = 0; j < 4; j++)
#pragma unroll
            for (int g = 0; g < 4; g++) acc[j][g] = 0.f;

        for (int kc = 0; kc < KA / 32; kc++) {
            // stage 32x128 weight chunk (4 gate segments of 32 cols)
            for (int i = tid; i < 32 * 128; i += NTHR) {
                const int r = i >> 7, c = i & 127;
                const int gg = c >> 5, uu = c & 31;
                const int row = kc * 32 + r;
                const int col = gg * 512 + u0 + uu;
                float w;
                if (KX > 0 && row < KX) w = Wk[row * G4U + col];
                else                    w = Wr[(row - KX) * G4U + col];
                Wsh[r * 128 + c] = w;
            }
            __syncthreads();
            const float* Arow = As + kc * 32;
#pragma unroll 8
            for (int r = 0; r < 32; r++) {
                const float a0 = Arow[(bg * 4 + 0) * KA + r];
                const float a1 = Arow[(bg * 4 + 1) * KA + r];
                const float a2 = Arow[(bg * 4 + 2) * KA + r];
                const float a3 = Arow[(bg * 4 + 3) * KA + r];
                const float w0 = Wsh[r * 128 + u];
                const float w1 = Wsh[r * 128 + 32 + u];
                const float w2 = Wsh[r * 128 + 64 + u];
                const float w3 = Wsh[r * 128 + 96 + u];
                acc[0][0] += a0 * w0; acc[0][1] += a0 * w1;
                acc[0][2] += a0 * w2; acc[0][3] += a0 * w3;
                acc[1][0] += a1 * w0; acc[1][1] += a1 * w1;
                acc[1][2] += a1 * w2; acc[1][3] += a1 * w3;
                acc[2][0] += a2 * w0; acc[2][1] += a2 * w1;
                acc[2][2] += a2 * w2; acc[2][3] += a2 * w3;
                acc[3][0] += a3 * w0; acc[3][1] += a3 * w1;
                acc[3][2] += a3 * w2; acc[3][3] += a3 * w3;
            }
            __syncthreads();
        }

        // epilogue: gates + state update
#pragma unroll
        for (int j = 0; j < 4; j++) {
            const int b = b0 + bg * 4 + j;
            float z0 = acc[j][0], z1 = acc[j][1], z2 = acc[j][2], z3 = acc[j][3];
            if (KX == 0) {
                const int xi = Xidx[b * cT + t];
                z0 += Etab[xi * G4U +        u0 + u] + Cb[b * G4U +        u0 + u];
                z1 += Etab[xi * G4U +  512 + u0 + u] + Cb[b * G4U +  512 + u0 + u];
                z2 += Etab[xi * G4U + 1024 + u0 + u] + Cb[b * G4U + 1024 + u0 + u];
                z3 += Etab[xi * G4U + 1536 + u0 + u] + Cb[b * G4U + 1536 + u0 + u];
            } else {
                z0 += bias[u0 + u];        z1 += bias[512 + u0 + u];
                z2 += bias[1024 + u0 + u]; z3 += bias[1536 + u0 + u];
            }
            const float ig = 1.f / (1.f + expf(-z0));
            const float fg = 1.f / (1.f + expf(-z1));
            const float gg = tanhf(z2);
            const float og = 1.f / (1.f + expf(-z3));
            creg[j] = fg * creg[j] + ig * gg;
            const float h2 = og * tanhf(creg[j]);
            seq_out[(b * cT + t) * cU + u0 + u] = h2;
            __stcg(&hnxt[b * cU + u0 + u], h2);
        }
        grid_bar(&g_bar[pass_id], (++nbar) * NCTA);
    }

#pragma unroll
    for (int j = 0; j < 4; j++)
        g_c[(b0 + bg * 4 + j) * cU + u0 + u] = creg[j];
}

// ----------------------- latent: mean / log_sigma / z ----------------------
__global__ void latz_kernel(const float* __restrict__ Wm, const float* __restrict__ bm,
                            const float* __restrict__ Ws, const float* __restrict__ bs,
                            const float* __restrict__ eps) {
    __shared__ float csh[cU];
    __shared__ float red[NTHR];
    const int b = blockIdx.x, tid = threadIdx.x;
    csh[tid]       = g_c[b * cU + tid];
    csh[tid + 256] = g_c[b * cU + tid + 256];
    __syncthreads();
    float term = 0.f;
    if (tid < cLAT) {
        float m = bm[tid], ls = bs[tid];
        for (int u = 0; u < cU; u++) {
            const float cv = csh[u];
            m  += cv * Wm[u * cLAT + tid];
            ls += cv * Ws[u * cLAT + tid];
        }
        g_z[b * cLAT + tid] = m + expf(0.5f * ls) * eps[b * cLAT + tid];
        term = 1.f + ls - m * m - expf(ls);
    }
    red[tid] = term;
    __syncthreads();
    for (int s = 128; s > 0; s >>= 1) {
        if (tid < s) red[tid] += red[tid + s];
        __syncthreads();
    }
    if (tid == 0) g_latpart[b] = red[0];
}

// ------------------------------- z projection ------------------------------
__global__ void zproj_kernel(const float* __restrict__ dec_k0) {
    __shared__ float zsh[cLAT];
    const int b = blockIdx.x, tid = threadIdx.x;
    if (tid < cLAT) zsh[tid] = g_z[b * cLAT + tid];
    __syncthreads();
    for (int n = tid; n < G4U; n += NTHR) {
        float acc = g_CbDec[b * G4U + n];
        for (int l = 0; l < cLAT; l++) acc += zsh[l] * dec_k0[l * G4U + n];
        g_Cz[b * G4U + n] = acc;
    }
}

// ----------------------- output logits + masked CE -------------------------
__global__ void ce_kernel(const float* __restrict__ Wo, const float* __restrict__ bo,
                          const int* __restrict__ Y, const int* __restrict__ Lv) {
    __shared__ float hsh[8][cU];
    __shared__ float wred[8];
    const int tid = threadIdx.x, w = tid >> 5, lane = tid & 31;
    const int gw = blockIdx.x * 8 + w;   // 4096 warps total
    const float* seq = g_seqB;           // decoder layer-2 output lives here
    float sum = 0.f;
    for (int j = 0; j < 8; j++) {
        const int idx = gw + j * 4096;   // 0..32767
        const int b = idx >> 7, t = idx & 127;
        const float* hp = &seq[(b * cT + t) * cU];
        for (int i = lane; i < cU; i += 32) hsh[w][i] = hp[i];
        __syncwarp();
        const int v0 = lane;
        const int v1 = 32 + lane;
        const int v1c = (v1 < cV) ? v1 : 0;
        float l0 = bo[v0];
        float l1 = bo[v1c];
        for (int u = 0; u < cU; u++) {
            const float hv = hsh[w][u];
            l0 += hv * Wo[u * cV + v0];
            l1 += hv * Wo[u * cV + v1c];
        }
        if (v1 >= cV) l1 = -1e30f;
        float mx = fmaxf(l0, l1);
        for (int o = 16; o; o >>= 1) mx = fmaxf(mx, __shfl_xor_sync(~0u, mx, o));
        float s = expf(l0 - mx) + ((v1 < cV) ? expf(l1 - mx) : 0.f);
        for (int o = 16; o; o >>= 1) s += __shfl_xor_sync(~0u, s, o);
        const float lse = mx + logf(s);
        const int y = Y[b * cT + t];
        const float ly = __shfl_sync(~0u, (y < 32) ? l0 : l1, y & 31);
        if (lane == 0 && t < Lv[b]) sum += (lse - ly);
        __syncwarp();
    }
    if (lane == 0) wred[w] = sum;
    __syncthreads();
    if (tid == 0) {
        float s = 0.f;
        for (int i = 0; i < 8; i++) s += wred[i];
        g_reconpart[blockIdx.x] = s;
    }
}

// ------------------------------- final reduce ------------------------------
__global__ void finish_kernel(float* __restrict__ out, int out_size) {
    __shared__ float red[NTHR];
    const int tid = threadIdx.x;
    float s = 0.f;
    for (int i = tid; i < 512; i += NTHR) s += g_reconpart[i];
    red[tid] = s;
    __syncthreads();
    for (int st = 128; st > 0; st >>= 1) {
        if (tid < st) red[tid] += red[tid + st];
        __syncthreads();
    }
    const float rsum = red[0];
    __syncthreads();
    float s2 = 0.f;
    for (int i = tid; i < cB; i += NTHR) s2 += g_latpart[i];
    red[tid] = s2;
    __syncthreads();
    for (int st = 128; st > 0; st >>= 1) {
        if (tid < st) red[tid] += red[tid + st];
        __syncthreads();
    }
    if (tid == 0) {
        const float recon = rsum / (float)(cB * cT);
        const float lat   = -0.5f * red[0] / (float)(cB * cLAT);
        out[0] = recon + lat;
        if (out_size > 1) out[1] = recon;
        if (out_size > 2) out[2] = lat;
    }
}

// --------------------------------- launch ----------------------------------
extern "C" void kernel_launch(void* const* d_in, const int* in_sizes, int n_in,
                              void* d_out, int out_size) {
    const int*   X       = (const int*)  d_in[0];
    const int*   Y       = (const int*)  d_in[1];
    const float* C       = (const float*)d_in[2];
    const int*   L       = (const int*)  d_in[3];
    const float* eps     = (const float*)d_in[4];
    const float* emb_enc = (const float*)d_in[5];
    const float* emb_dec = (const float*)d_in[6];
    const float* enc_k0  = (const float*)d_in[7];
    const float* enc_rk0 = (const float*)d_in[8];
    // enc_b0 = d_in[9] (folded into CbEnc)
    const float* enc_k1  = (const float*)d_in[10];
    const float* enc_rk1 = (const float*)d_in[11];
    const float* enc_b1  = (const float*)d_in[12];
    const float* enc_k2  = (const float*)d_in[13];
    const float* enc_rk2 = (const float*)d_in[14];
    const float* enc_b2  = (const float*)d_in[15];
    const float* dec_k0  = (const float*)d_in[16];
    const float* dec_rk0 = (const float*)d_in[17];
    // dec_b0 = d_in[18] (folded into CbDec)
    const float* dec_k1  = (const float*)d_in[19];
    const float* dec_rk1 = (const float*)d_in[20];
    const float* dec_b1  = (const float*)d_in[21];
    const float* dec_k2  = (const float*)d_in[22];
    const float* dec_rk2 = (const float*)d_in[23];
    const float* dec_b2  = (const float*)d_in[24];
    const float* Wm      = (const float*)d_in[25];
    const float* bm      = (const float*)d_in[26];
    const float* Ws      = (const float*)d_in[27];
    const float* bs      = (const float*)d_in[28];
    const float* Wo      = (const float*)d_in[29];
    const float* bo      = (const float*)d_in[30];

    const size_t SMA = (size_t)(NB * 512  + 32 * 128) * sizeof(float);  //  80 KB
    const size_t SMB = (size_t)(NB * 1024 + 32 * 128) * sizeof(float);  // 144 KB
    cudaFuncSetAttribute((const void*)rec_kernel<0>,
                         cudaFuncAttributeMaxDynamicSharedMemorySize, (int)SMA);
    cudaFuncSetAttribute((const void*)rec_kernel<512>,
                         cudaFuncAttributeMaxDynamicSharedMemorySize, (int)SMB);

    prep_kernel<<<605, NTHR>>>(emb_enc, emb_dec, enc_k0, dec_k0,
                               (const float*)d_in[9], (const float*)d_in[18], C);

    // ---- encoder ----
    rec_kernel<0>  <<<NCTA, NTHR, SMA>>>(nullptr, enc_rk0, nullptr, X, 0, 0, 0, 0);
    rec_kernel<512><<<NCTA, NTHR, SMB>>>(enc_k1, enc_rk1, enc_b1, nullptr, 0, 1, 0, 1);
    rec_kernel<512><<<NCTA, NTHR, SMB>>>(enc_k2, enc_rk2, enc_b2, nullptr, 1, 0, 0, 2);

    // ---- latent ----
    latz_kernel<<<cB, NTHR>>>(Wm, bm, Ws, bs, eps);
    zproj_kernel<<<cB, NTHR>>>(dec_k0);

    // ---- decoder ----
    rec_kernel<0>  <<<NCTA, NTHR, SMA>>>(nullptr, dec_rk0, nullptr, X, 0, 1, 1, 3);
    rec_kernel<512><<<NCTA, NTHR, SMB>>>(dec_k1, dec_rk1, dec_b1, nullptr, 1, 0, 1, 4);
    rec_kernel<512><<<NCTA, NTHR, SMB>>>(dec_k2, dec_rk2, dec_b2, nullptr, 0, 1, 1, 5);

    // ---- losses ----
    ce_kernel<<<512, NTHR>>>(Wo, bo, Y, L);
    finish_kernel<<<1, NTHR>>>((float*)d_out, out_size);
}

// round 2
// speedup vs baseline: 4.0750x; 4.0750x over previous
#include <cuda_runtime.h>
#include <cstdint>
#include <cstddef>

// ---------------------------------------------------------------------------
// CVAE forward, Round 2: tf32 mma.sync everywhere.
//  - input projections hoisted out of the recurrence (batched GEMM "preproj")
//  - recurrent kernel: persistent permuted weights in SMEM (128KB), per-step
//    K=512 h@rk via m16n8k8 tf32 mma, grid barrier per step (128 CTAs)
// B=256 T=128 U=512 LAT=200 V=42 P=3
// ---------------------------------------------------------------------------

constexpr int cB = 256, cT = 128, cU = 512, cLAT = 200, cV = 42, cP = 3;
constexpr int G4U = 2048;
constexpr int NCTA = 128, NTHR = 256;

// ------------------------------- scratch -----------------------------------
__device__ float g_seqA[cB * cT * cU];            // 64 MB
__device__ float g_seqB[cB * cT * cU];            // 64 MB
__device__ float g_pre[(size_t)cB * cT * G4U];    // 256 MB
__device__ float g_h[2][cB * cU];
__device__ float g_c[cB * cU];
__device__ float g_Eenc[cV * G4U];
__device__ float g_Edec[cV * G4U];
__device__ float g_CbEnc[cB * G4U];
__device__ float g_CbDec[cB * G4U];
__device__ float g_Cz[cB * G4U];
__device__ float g_z[cB * cLAT];
__device__ float g_latpart[cB];
__device__ float g_reconpart[512];
__device__ unsigned g_bar[8];

// ------------------------------ helpers ------------------------------------
__device__ __forceinline__ unsigned f2tf(float f) {
    unsigned u;
    asm("cvt.rna.tf32.f32 %0, %1;" : "=r"(u) : "f"(f));
    return u;
}

__device__ __forceinline__ void mma8(float* c, unsigned a0, unsigned a1,
                                     unsigned a2, unsigned a3,
                                     unsigned b0, unsigned b1) {
    asm volatile(
        "mma.sync.aligned.m16n8k8.row.col.f32.tf32.tf32.f32 "
        "{%0,%1,%2,%3}, {%4,%5,%6,%7}, {%8,%9}, {%0,%1,%2,%3};"
        : "+f"(c[0]), "+f"(c[1]), "+f"(c[2]), "+f"(c[3])
        : "r"(a0), "r"(a1), "r"(a2), "r"(a3), "r"(b0), "r"(b1));
}

__device__ __forceinline__ void grid_bar(unsigned* ctr, unsigned target) {
    __threadfence();
    __syncthreads();
    if (threadIdx.x == 0) {
        atomicAdd(ctr, 1u);
        while (*(volatile unsigned*)ctr < target) __nanosleep(64);
        __threadfence();
    }
    __syncthreads();
}

// ------------------------------ prep kernel --------------------------------
__global__ void prep_kernel(const float* __restrict__ emb_enc,
                            const float* __restrict__ emb_dec,
                            const float* __restrict__ enc_k0,
                            const float* __restrict__ dec_k0,
                            const float* __restrict__ enc_b0,
                            const float* __restrict__ dec_b0,
                            const float* __restrict__ Cmat) {
    const int bid = blockIdx.x, tid = threadIdx.x;
    if (bid < 42) {
        const int v = bid;
        for (int n = tid; n < G4U; n += NTHR) {
            float acc = 0.f;
            for (int l = 0; l < cLAT; l++)
                acc += emb_enc[v * cLAT + l] * enc_k0[l * G4U + n];
            g_Eenc[v * G4U + n] = acc;
        }
    } else if (bid < 84) {
        const int v = bid - 42;
        for (int n = tid; n < G4U; n += NTHR) {
            float acc = 0.f;
            for (int l = 0; l < cLAT; l++)
                acc += emb_dec[v * cLAT + l] * dec_k0[(cLAT + l) * G4U + n];
            g_Edec[v * G4U + n] = acc;
        }
    } else if (bid < 340) {
        const int b = bid - 84;
        for (int n = tid; n < G4U; n += NTHR) {
            float acc = enc_b0[n];
            for (int p = 0; p < cP; p++)
                acc += Cmat[b * cP + p] * enc_k0[(cLAT + p) * G4U + n];
            g_CbEnc[b * G4U + n] = acc;
        }
    } else if (bid < 596) {
        const int b = bid - 340;
        for (int n = tid; n < G4U; n += NTHR) {
            float acc = dec_b0[n];
            for (int p = 0; p < cP; p++)
                acc += Cmat[b * cP + p] * dec_k0[(2 * cLAT + p) * G4U + n];
            g_CbDec[b * G4U + n] = acc;
        }
    } else {
        if (tid < 8) g_bar[tid] = 0u;
    }
}

// ---------------------- preproj: pre = seq @ Wk + bias ---------------------
// M=32768, N=2048, K=512. CTA tile 128x128, 256 threads, 8 warps (warp 32x64).
// K chunks of 32, double-buffered permuted smem, tf32 mma.
__global__ __launch_bounds__(256, 1)
void preproj_kernel(int sel_in, const float* __restrict__ Wk,
                    const float* __restrict__ bias) {
    extern __shared__ unsigned sm[];
    unsigned* Asm = sm;          // [2][8 strip][2 kb][2 half][32][4] = 2*4096
    unsigned* Bsm = sm + 8192;   // [2][16 grp][2 kb][32][4]         = 2*4096

    const float* Aseq = sel_in ? g_seqB : g_seqA;
    const int tid = threadIdx.x, lane = tid & 31, w = tid >> 5;
    const int wm = w & 3, wn = w >> 2;
    const int n0 = blockIdx.x * 128;
    const int m0 = blockIdx.y * 128;

    float acc[2][8][4];
#pragma unroll
    for (int s = 0; s < 2; s++)
#pragma unroll
        for (int g = 0; g < 8; g++)
#pragma unroll
            for (int q = 0; q < 4; q++) acc[s][g][q] = 0.f;

    float ra[16], rb[16];

    // ---- load chunk 0 ----
#pragma unroll
    for (int j = 0; j < 16; j++) {
        int i = tid + j * 256;
        int row = i >> 5, k = i & 31;
        ra[j] = Aseq[(size_t)(m0 + row) * 512 + k];
        int kk = i >> 7, n = i & 127;
        rb[j] = Wk[(size_t)kk * G4U + n0 + n];
    }
    // ---- store chunk 0 ----
    {
#pragma unroll
        for (int j = 0; j < 16; j++) {
            int i = tid + j * 256;
            {
                int row = i >> 5, k = i & 31;
                int strip = row >> 4, rr = row & 15;
                int kb = (k >> 4) & 1, half = (k >> 3) & 1;
                int ln = ((rr & 7) << 2) | (k & 3);
                int slot = (rr >> 3) | (((k >> 2) & 1) << 1);
                Asm[(((strip * 2 + kb) * 2 + half) * 32 + ln) * 4 + slot] = f2tf(ra[j]);
            }
            {
                int kk = i >> 7, n = i & 127;
                int grp = n >> 3, kb = (kk >> 4) & 1;
                int ln = ((n & 7) << 2) | (kk & 3);
                int slot = (kk >> 2) & 3;
                Bsm[((grp * 2 + kb) * 32 + ln) * 4 + slot] = f2tf(rb[j]);
            }
        }
    }
    __syncthreads();

    for (int kc = 0; kc < 16; kc++) {
        if (kc < 15) {
#pragma unroll
            for (int j = 0; j < 16; j++) {
                int i = tid + j * 256;
                int row = i >> 5, k = i & 31;
                ra[j] = Aseq[(size_t)(m0 + row) * 512 + (kc + 1) * 32 + k];
                int kk = i >> 7, n = i & 127;
                rb[j] = Wk[(size_t)((kc + 1) * 32 + kk) * G4U + n0 + n];
            }
        }
        const unsigned* Ab0 = Asm + (kc & 1) * 4096;
        const unsigned* Bb0 = Bsm + (kc & 1) * 4096;
#pragma unroll
        for (int kb = 0; kb < 2; kb++) {
            uint4 alo[2], ahi[2];
#pragma unroll
            for (int s = 0; s < 2; s++) {
                const unsigned* Ab = Ab0 + (((wm * 2 + s) * 2 + kb) * 2) * 128;
                alo[s] = *(const uint4*)(Ab + lane * 4);
                ahi[s] = *(const uint4*)(Ab + 128 + lane * 4);
            }
#pragma unroll
            for (int g = 0; g < 8; g++) {
                uint4 bv = *(const uint4*)(Bb0 + (((wn * 8 + g) * 2 + kb) * 32 + lane) * 4);
#pragma unroll
                for (int s = 0; s < 2; s++) {
                    mma8(acc[s][g], alo[s].x, alo[s].y, alo[s].z, alo[s].w, bv.x, bv.y);
                    mma8(acc[s][g], ahi[s].x, ahi[s].y, ahi[s].z, ahi[s].w, bv.z, bv.w);
                }
            }
        }
        if (kc < 15) {
            __syncthreads();
            unsigned* Ad = Asm + ((kc + 1) & 1) * 4096;
            unsigned* Bd = Bsm + ((kc + 1) & 1) * 4096;
#pragma unroll
            for (int j = 0; j < 16; j++) {
                int i = tid + j * 256;
                {
                    int row = i >> 5, k = i & 31;
                    int strip = row >> 4, rr = row & 15;
                    int kb = (k >> 4) & 1, half = (k >> 3) & 1;
                    int ln = ((rr & 7) << 2) | (k & 3);
                    int slot = (rr >> 3) | (((k >> 2) & 1) << 1);
                    Ad[(((strip * 2 + kb) * 2 + half) * 32 + ln) * 4 + slot] = f2tf(ra[j]);
                }
                {
                    int kk = i >> 7, n = i & 127;
                    int grp = n >> 3, kb = (kk >> 4) & 1;
                    int ln = ((n & 7) << 2) | (kk & 3);
                    int slot = (kk >> 2) & 3;
                    Bd[((grp * 2 + kb) * 32 + ln) * 4 + slot] = f2tf(rb[j]);
                }
            }
            __syncthreads();
        }
    }

    // ---- epilogue ----
#pragma unroll
    for (int s = 0; s < 2; s++) {
#pragma unroll
        for (int g = 0; g < 8; g++) {
            int row = m0 + wm * 32 + s * 16 + (lane >> 2);
            int col = n0 + wn * 64 + g * 8 + (lane & 3) * 2;
            float b0 = __ldg(&bias[col]);
            float b1 = __ldg(&bias[col + 1]);
            g_pre[(size_t)row * G4U + col]           = acc[s][g][0] + b0;
            g_pre[(size_t)row * G4U + col + 1]       = acc[s][g][1] + b1;
            g_pre[(size_t)(row + 8) * G4U + col]     = acc[s][g][2] + b0;
            g_pre[(size_t)(row + 8) * G4U + col + 1] = acc[s][g][3] + b1;
        }
    }
}

// ----------------------- recurrent kernel (tf32 mma) -----------------------
// Grid: 128 CTAs = 4 btiles(64 rows) x 32 utiles(16 units -> 64 gate-cols).
// Persistent permuted W (128KB smem). Per step: stage h (K=512) through a
// double-buffered permuted smem pipeline (chunks of 64), mma, gate epilogue.
constexpr int REC_SMEM = (32768 + 8192 + 64 * 65) * 4;  // 180,480 B

template <bool L0>
__global__ __launch_bounds__(256, 1)
void rec2_kernel(const float* __restrict__ Wr, const int* __restrict__ Xidx,
                 int sel_dec, int sel_out, int pass_id) {
    extern __shared__ unsigned sm[];
    unsigned* Wp = sm;                    // [8 grp][32 kbG][32 ln][4]
    unsigned* Hb = sm + 32768;            // [2 buf][4 strip][4 kb][2 half][32][4]
    float* zs = (float*)(sm + 32768 + 8192);  // [64][65]

    const int tid = threadIdx.x, lane = tid & 31, w = tid >> 5;
    const int wm = w & 3, wn = w >> 2;
    const int b0 = (blockIdx.x >> 5) * 64;
    const int u0 = (blockIdx.x & 31) * 16;

    float* seq_out = sel_out ? g_seqB : g_seqA;
    const float* Etab = sel_dec ? g_Edec : g_Eenc;
    const float* Cb = sel_dec ? g_Cz : g_CbEnc;

    // ---- permute W into persistent smem (once) ----
    for (int i = tid; i < 512 * 64; i += 256) {
        int k = i >> 6, n = i & 63;
        int gate = n >> 4, uu = n & 15;
        float wv = Wr[(size_t)k * G4U + gate * 512 + u0 + uu];
        int grp = n >> 3, kb = k >> 4;
        int ln = ((n & 7) << 2) | (k & 3);
        int slot = (k >> 2) & 3;
        Wp[((grp * 32 + kb) * 32 + ln) * 4 + slot] = f2tf(wv);
    }
    // ---- zero my h slices ----
    for (int i = tid; i < 1024; i += 256) {
        int bb = i >> 4, uu = i & 15;
        g_h[0][(b0 + bb) * cU + u0 + uu] = 0.f;
        g_h[1][(b0 + bb) * cU + u0 + uu] = 0.f;
    }
    unsigned nbar = 0;
    grid_bar(&g_bar[pass_id], (++nbar) * NCTA);

    float cst[4] = {0.f, 0.f, 0.f, 0.f};
    float r[16];

    for (int t = 0; t < cT; t++) {
        const float* hc = (t & 1) ? g_h[1] : g_h[0];
        float* hn = (t & 1) ? g_h[0] : g_h[1];

        float acc[4][4];
#pragma unroll
        for (int g = 0; g < 4; g++)
#pragma unroll
            for (int q = 0; q < 4; q++) acc[g][q] = 0.f;

        // prefetch + store chunk 0
#pragma unroll
        for (int j = 0; j < 16; j++) {
            int i = tid + j * 256;
            int row = i >> 6, k = i & 63;
            r[j] = __ldcg(&hc[(b0 + row) * cU + k]);
        }
#pragma unroll
        for (int j = 0; j < 16; j++) {
            int i = tid + j * 256;
            int row = i >> 6, k = i & 63;
            int strip = row >> 4, rr = row & 15;
            int kb = k >> 4, half = (k >> 3) & 1;
            int ln = ((rr & 7) << 2) | (k & 3);
            int slot = (rr >> 3) | (((k >> 2) & 1) << 1);
            Hb[(((strip * 4 + kb) * 2 + half) * 32 + ln) * 4 + slot] = f2tf(r[j]);
        }
        __syncthreads();

        for (int kc = 0; kc < 8; kc++) {
            if (kc < 7) {
#pragma unroll
                for (int j = 0; j < 16; j++) {
                    int i = tid + j * 256;
                    int row = i >> 6, k = i & 63;
                    r[j] = __ldcg(&hc[(b0 + row) * cU + (kc + 1) * 64 + k]);
                }
            }
            const unsigned* Hbuf = Hb + (kc & 1) * 4096;
#pragma unroll
            for (int kb = 0; kb < 4; kb++) {
                const unsigned* Ab = Hbuf + ((wm * 4 + kb) * 2) * 128;
                uint4 alo = *(const uint4*)(Ab + lane * 4);
                uint4 ahi = *(const uint4*)(Ab + 128 + lane * 4);
                int kbg = kc * 4 + kb;
#pragma unroll
                for (int g = 0; g < 4; g++) {
                    uint4 bv = *(const uint4*)(Wp + (((wn * 4 + g) * 32 + kbg) * 32 + lane) * 4);
                    mma8(acc[g], alo.x, alo.y, alo.z, alo.w, bv.x, bv.y);
                    mma8(acc[g], ahi.x, ahi.y, ahi.z, ahi.w, bv.z, bv.w);
                }
            }
            if (kc < 7) {
                __syncthreads();
                unsigned* Hd = Hb + ((kc + 1) & 1) * 4096;
#pragma unroll
                for (int j = 0; j < 16; j++) {
                    int i = tid + j * 256;
                    int row = i >> 6, k = i & 63;
                    int strip = row >> 4, rr = row & 15;
                    int kb = k >> 4, half = (k >> 3) & 1;
                    int ln = ((rr & 7) << 2) | (k & 3);
                    int slot = (rr >> 3) | (((k >> 2) & 1) << 1);
                    Hd[(((strip * 4 + kb) * 2 + half) * 32 + ln) * 4 + slot] = f2tf(r[j]);
                }
                __syncthreads();
            }
        }

        // ---- epilogue: z -> smem ----
        {
            int qr = wm * 16 + (lane >> 2);
            int qc = wn * 32 + (lane & 3) * 2;
#pragma unroll
            for (int g = 0; g < 4; g++) {
                zs[qr * 65 + qc + g * 8]           = acc[g][0];
                zs[qr * 65 + qc + g * 8 + 1]       = acc[g][1];
                zs[(qr + 8) * 65 + qc + g * 8]     = acc[g][2];
                zs[(qr + 8) * 65 + qc + g * 8 + 1] = acc[g][3];
            }
        }
        __syncthreads();

        // ---- gates + state update ----
#pragma unroll
        for (int j = 0; j < 4; j++) {
            int idx = tid + j * 256;
            int bl = idx >> 4, ul = idx & 15;
            int b = b0 + bl;
            float zi = zs[bl * 65 + ul];
            float zf = zs[bl * 65 + 16 + ul];
            float zg = zs[bl * 65 + 32 + ul];
            float zo = zs[bl * 65 + 48 + ul];
            if (L0) {
                int xi = Xidx[b * cT + t];
                zi += Etab[xi * G4U + u0 + ul]        + Cb[b * G4U + u0 + ul];
                zf += Etab[xi * G4U + 512 + u0 + ul]  + Cb[b * G4U + 512 + u0 + ul];
                zg += Etab[xi * G4U + 1024 + u0 + ul] + Cb[b * G4U + 1024 + u0 + ul];
                zo += Etab[xi * G4U + 1536 + u0 + ul] + Cb[b * G4U + 1536 + u0 + ul];
            } else {
                const float* pp = &g_pre[((size_t)b * cT + t) * G4U];
                zi += pp[u0 + ul];
                zf += pp[512 + u0 + ul];
                zg += pp[1024 + u0 + ul];
                zo += pp[1536 + u0 + ul];
            }
            float ig = 1.f / (1.f + expf(-zi));
            float fg = 1.f / (1.f + expf(-zf));
            float gg = tanhf(zg);
            float og = 1.f / (1.f + expf(-zo));
            cst[j] = fg * cst[j] + ig * gg;
            float h2 = og * tanhf(cst[j]);
            seq_out[((size_t)b * cT + t) * cU + u0 + ul] = h2;
            __stcg(&hn[b * cU + u0 + ul], h2);
        }
        grid_bar(&g_bar[pass_id], (++nbar) * NCTA);
    }

#pragma unroll
    for (int j = 0; j < 4; j++) {
        int idx = tid + j * 256;
        int bl = idx >> 4, ul = idx & 15;
        g_c[(b0 + bl) * cU + u0 + ul] = cst[j];
    }
}

// ----------------------- latent: mean / log_sigma / z ----------------------
__global__ void latz_kernel(const float* __restrict__ Wm, const float* __restrict__ bm,
                            const float* __restrict__ Ws, const float* __restrict__ bs,
                            const float* __restrict__ eps) {
    __shared__ float csh[cU];
    __shared__ float red[NTHR];
    const int b = blockIdx.x, tid = threadIdx.x;
    csh[tid] = g_c[b * cU + tid];
    csh[tid + 256] = g_c[b * cU + tid + 256];
    __syncthreads();
    float term = 0.f;
    if (tid < cLAT) {
        float m = bm[tid], ls = bs[tid];
        for (int u = 0; u < cU; u++) {
            const float cv = csh[u];
            m += cv * Wm[u * cLAT + tid];
            ls += cv * Ws[u * cLAT + tid];
        }
        g_z[b * cLAT + tid] = m + expf(0.5f * ls) * eps[b * cLAT + tid];
        term = 1.f + ls - m * m - expf(ls);
    }
    red[tid] = term;
    __syncthreads();
    for (int s = 128; s > 0; s >>= 1) {
        if (tid < s) red[tid] += red[tid + s];
        __syncthreads();
    }
    if (tid == 0) g_latpart[b] = red[0];
}

// ------------------------------- z projection ------------------------------
__global__ void zproj_kernel(const float* __restrict__ dec_k0) {
    __shared__ float zsh[cLAT];
    const int b = blockIdx.x, tid = threadIdx.x;
    if (tid < cLAT) zsh[tid] = g_z[b * cLAT + tid];
    __syncthreads();
    for (int n = tid; n < G4U; n += NTHR) {
        float acc = g_CbDec[b * G4U + n];
        for (int l = 0; l < cLAT; l++) acc += zsh[l] * dec_k0[l * G4U + n];
        g_Cz[b * G4U + n] = acc;
    }
}

// ----------------------- output logits + masked CE -------------------------
__global__ void ce_kernel(const float* __restrict__ Wo, const float* __restrict__ bo,
                          const int* __restrict__ Y, const int* __restrict__ Lv) {
    __shared__ float hsh[8][cU];
    __shared__ float wred[8];
    const int tid = threadIdx.x, w = tid >> 5, lane = tid & 31;
    const int gw = blockIdx.x * 8 + w;
    const float* seq = g_seqA;   // decoder layer-2 output
    float sum = 0.f;
    for (int j = 0; j < 8; j++) {
        const int idx = gw + j * 4096;
        const int b = idx >> 7, t = idx & 127;
        const float* hp = &seq[((size_t)b * cT + t) * cU];
        for (int i = lane; i < cU; i += 32) hsh[w][i] = hp[i];
        __syncwarp();
        const int v0 = lane;
        const int v1 = 32 + lane;
        const int v1c = (v1 < cV) ? v1 : 0;
        float l0 = bo[v0];
        float l1 = bo[v1c];
        for (int u = 0; u < cU; u++) {
            const float hv = hsh[w][u];
            l0 += hv * Wo[u * cV + v0];
            l1 += hv * Wo[u * cV + v1c];
        }
        if (v1 >= cV) l1 = -1e30f;
        float mx = fmaxf(l0, l1);
        for (int o = 16; o; o >>= 1) mx = fmaxf(mx, __shfl_xor_sync(~0u, mx, o));
        float s = expf(l0 - mx) + ((v1 < cV) ? expf(l1 - mx) : 0.f);
        for (int o = 16; o; o >>= 1) s += __shfl_xor_sync(~0u, s, o);
        const float lse = mx + logf(s);
        const int y = Y[b * cT + t];
        const float ly = __shfl_sync(~0u, (y < 32) ? l0 : l1, y & 31);
        if (lane == 0 && t < Lv[b]) sum += (lse - ly);
        __syncwarp();
    }
    if (lane == 0) wred[w] = sum;
    __syncthreads();
    if (tid == 0) {
        float s = 0.f;
        for (int i = 0; i < 8; i++) s += wred[i];
        g_reconpart[blockIdx.x] = s;
    }
}

// ------------------------------- final reduce ------------------------------
__global__ void finish_kernel(float* __restrict__ out, int out_size) {
    __shared__ float red[NTHR];
    const int tid = threadIdx.x;
    float s = 0.f;
    for (int i = tid; i < 512; i += NTHR) s += g_reconpart[i];
    red[tid] = s;
    __syncthreads();
    for (int st = 128; st > 0; st >>= 1) {
        if (tid < st) red[tid] += red[tid + st];
        __syncthreads();
    }
    const float rsum = red[0];
    __syncthreads();
    float s2 = 0.f;
    for (int i = tid; i < cB; i += NTHR) s2 += g_latpart[i];
    red[tid] = s2;
    __syncthreads();
    for (int st = 128; st > 0; st >>= 1) {
        if (tid < st) red[tid] += red[tid + st];
        __syncthreads();
    }
    if (tid == 0) {
        const float recon = rsum / (float)(cB * cT);
        const float lat = -0.5f * red[0] / (float)(cB * cLAT);
        out[0] = recon + lat;
        if (out_size > 1) out[1] = recon;
        if (out_size > 2) out[2] = lat;
    }
}

// --------------------------------- launch ----------------------------------
extern "C" void kernel_launch(void* const* d_in, const int* in_sizes, int n_in,
                              void* d_out, int out_size) {
    const int* X = (const int*)d_in[0];
    const int* Y = (const int*)d_in[1];
    const float* C = (const float*)d_in[2];
    const int* L = (const int*)d_in[3];
    const float* eps = (const float*)d_in[4];
    const float* emb_enc = (const float*)d_in[5];
    const float* emb_dec = (const float*)d_in[6];
    const float* enc_k0 = (const float*)d_in[7];
    const float* enc_rk0 = (const float*)d_in[8];
    const float* enc_b0 = (const float*)d_in[9];
    const float* enc_k1 = (const float*)d_in[10];
    const float* enc_rk1 = (const float*)d_in[11];
    const float* enc_b1 = (const float*)d_in[12];
    const float* enc_k2 = (const float*)d_in[13];
    const float* enc_rk2 = (const float*)d_in[14];
    const float* enc_b2 = (const float*)d_in[15];
    const float* dec_k0 = (const float*)d_in[16];
    const float* dec_rk0 = (const float*)d_in[17];
    const float* dec_b0 = (const float*)d_in[18];
    const float* dec_k1 = (const float*)d_in[19];
    const float* dec_rk1 = (const float*)d_in[20];
    const float* dec_b1 = (const float*)d_in[21];
    const float* dec_k2 = (const float*)d_in[22];
    const float* dec_rk2 = (const float*)d_in[23];
    const float* dec_b2 = (const float*)d_in[24];
    const float* Wm = (const float*)d_in[25];
    const float* bm = (const float*)d_in[26];
    const float* Ws = (const float*)d_in[27];
    const float* bs = (const float*)d_in[28];
    const float* Wo = (const float*)d_in[29];
    const float* bo = (const float*)d_in[30];

    const int SMG = 16384 * 4;  // 64KB for preproj
    cudaFuncSetAttribute((const void*)preproj_kernel,
                         cudaFuncAttributeMaxDynamicSharedMemorySize, SMG);
    cudaFuncSetAttribute((const void*)rec2_kernel<true>,
                         cudaFuncAttributeMaxDynamicSharedMemorySize, REC_SMEM);
    cudaFuncSetAttribute((const void*)rec2_kernel<false>,
                         cudaFuncAttributeMaxDynamicSharedMemorySize, REC_SMEM);

    prep_kernel<<<597, NTHR>>>(emb_enc, emb_dec, enc_k0, dec_k0, enc_b0, dec_b0, C);

    const dim3 gg(16, 256);

    // ---- encoder ----
    rec2_kernel<true><<<NCTA, NTHR, REC_SMEM>>>(enc_rk0, X, 0, /*out*/0, 0);
    preproj_kernel<<<gg, NTHR, SMG>>>(/*in A*/0, enc_k1, enc_b1);
    rec2_kernel<false><<<NCTA, NTHR, REC_SMEM>>>(enc_rk1, nullptr, 0, /*out*/1, 1);
    preproj_kernel<<<gg, NTHR, SMG>>>(/*in B*/1, enc_k2, enc_b2);
    rec2_kernel<false><<<NCTA, NTHR, REC_SMEM>>>(enc_rk2, nullptr, 0, /*out*/0, 2);

    // ---- latent ----
    latz_kernel<<<cB, NTHR>>>(Wm, bm, Ws, bs, eps);
    zproj_kernel<<<cB, NTHR>>>(dec_k0);

    // ---- decoder ----
    rec2_kernel<true><<<NCTA, NTHR, REC_SMEM>>>(dec_rk0, X, 1, /*out*/0, 3);
    preproj_kernel<<<gg, NTHR, SMG>>>(/*in A*/0, dec_k1, dec_b1);
    rec2_kernel<false><<<NCTA, NTHR, REC_SMEM>>>(dec_rk1, nullptr, 0, /*out*/1, 4);
    preproj_kernel<<<gg, NTHR, SMG>>>(/*in B*/1, dec_k2, dec_b2);
    rec2_kernel<false><<<NCTA, NTHR, REC_SMEM>>>(dec_rk2, nullptr, 0, /*out*/0, 5);

    // ---- losses ----
    ce_kernel<<<512, NTHR>>>(Wo, bo, Y, L);
    finish_kernel<<<1, NTHR>>>((float*)d_out, out_size);
}

// round 3
// speedup vs baseline: 7.6561x; 1.8788x over previous
#include <cuda_runtime.h>
#include <cuda_bf16.h>
#include <cstdint>
#include <cstddef>

// ---------------------------------------------------------------------------
// CVAE forward, Round 3: bf16 mma, fused next-layer input projection,
// 32-CTA scoped barriers, cp.async staging of pre-permuted bf16 h images.
// B=256 T=128 U=512 LAT=200 V=42 P=3
// ---------------------------------------------------------------------------

constexpr int cB = 256, cT = 128, cU = 512, cLAT = 200, cV = 42, cP = 3;
constexpr int G4U = 2048;
constexpr int NTHR = 256, NCTA = 128;

// ------------------------------- scratch -----------------------------------
__device__ float g_pre[(size_t)cB * cT * G4U];           // 256 MB
__device__ __nv_bfloat16 g_seq[(size_t)cB * cT * cU];    // dec layer2 out
__device__ __nv_bfloat16 g_himg[4][2][32768];            // per-bgroup h image
__device__ float g_c[cB * cU];
__device__ float g_Eenc[cV * G4U];
__device__ float g_Edec[cV * G4U];
__device__ float g_CbEnc[cB * G4U];
__device__ float g_CbDec[cB * G4U];
__device__ float g_Cz[cB * G4U];
__device__ float g_z[cB * cLAT];
__device__ float g_latpart[cB];
__device__ float g_reconpart[512];
__device__ unsigned g_bar2[24];

// ------------------------------ helpers ------------------------------------
__device__ __forceinline__ void cpa16(void* d, const void* s) {
    unsigned ds = (unsigned)__cvta_generic_to_shared(d);
    asm volatile("cp.async.cg.shared.global [%0], [%1], 16;" :: "r"(ds), "l"(s));
}

__device__ __forceinline__ void mma16(float* c, uint4 a, uint2 b) {
    asm volatile(
        "mma.sync.aligned.m16n8k16.row.col.f32.bf16.bf16.f32 "
        "{%0,%1,%2,%3},{%4,%5,%6,%7},{%8,%9},{%0,%1,%2,%3};"
        : "+f"(c[0]), "+f"(c[1]), "+f"(c[2]), "+f"(c[3])
        : "r"(a.x), "r"(a.y), "r"(a.z), "r"(a.w), "r"(b.x), "r"(b.y));
}

__device__ __forceinline__ void bar32(unsigned* ctr, unsigned target) {
    __threadfence();
    __syncthreads();
    if (threadIdx.x == 0) {
        atomicAdd(ctr, 1u);
        while (*(volatile unsigned*)ctr < target) {}
        __threadfence();
    }
    __syncthreads();
}

// ------------------------------ prep kernel --------------------------------
__global__ void prep_kernel(const float* __restrict__ emb_enc,
                            const float* __restrict__ emb_dec,
                            const float* __restrict__ enc_k0,
                            const float* __restrict__ dec_k0,
                            const float* __restrict__ enc_b0,
                            const float* __restrict__ dec_b0,
                            const float* __restrict__ Cmat) {
    const int bid = blockIdx.x, tid = threadIdx.x;
    if (bid < 42) {
        const int v = bid;
        for (int n = tid; n < G4U; n += NTHR) {
            float acc = 0.f;
            for (int l = 0; l < cLAT; l++)
                acc += emb_enc[v * cLAT + l] * enc_k0[l * G4U + n];
            g_Eenc[v * G4U + n] = acc;
        }
    } else if (bid < 84) {
        const int v = bid - 42;
        for (int n = tid; n < G4U; n += NTHR) {
            float acc = 0.f;
            for (int l = 0; l < cLAT; l++)
                acc += emb_dec[v * cLAT + l] * dec_k0[(cLAT + l) * G4U + n];
            g_Edec[v * G4U + n] = acc;
        }
    } else if (bid < 340) {
        const int b = bid - 84;
        for (int n = tid; n < G4U; n += NTHR) {
            float acc = enc_b0[n];
            for (int p = 0; p < cP; p++)
                acc += Cmat[b * cP + p] * enc_k0[(cLAT + p) * G4U + n];
            g_CbEnc[b * G4U + n] = acc;
        }
    } else if (bid < 596) {
        const int b = bid - 340;
        for (int n = tid; n < G4U; n += NTHR) {
            float acc = dec_b0[n];
            for (int p = 0; p < cP; p++)
                acc += Cmat[b * cP + p] * dec_k0[(2 * cLAT + p) * G4U + n];
            g_CbDec[b * G4U + n] = acc;
        }
    } else {
        if (tid < 24) g_bar2[tid] = 0u;
    }
}

// --------------------------- recurrent kernel ------------------------------
// 128 CTAs = 4 bgroups(64 rows) x 32 utiles(16 units -> 64 gate cols).
// Per step: cp.async staged permuted bf16 h image (4 quarters), mma h@Wr
// (recurrence) and, if FUSE, h@Wk (next layer's input projection for t-1).
template <bool L0, bool FUSE, bool WRSEQ>
__global__ __launch_bounds__(256, 1)
void rec3_kernel(const float* __restrict__ Wr, const float* __restrict__ Wk,
                 const float* __restrict__ bnext, const int* __restrict__ Xidx,
                 int sel_dec, int pass_id) {
    extern __shared__ unsigned sm[];
    unsigned* WrS = sm;                                   // 64KB
    unsigned* WkS = sm + 16384;                           // 64KB if FUSE
    constexpr int AOFF = FUSE ? 32768 : 16384;
    unsigned* Asm = sm + AOFF;                            // 64KB
    float* zs = (float*)(sm + AOFF + 16384);              // 64*65 f32

    const int tid = threadIdx.x, lane = tid & 31, w = tid >> 5;
    const int wm = w & 3, wn = w >> 2;
    const int bg = blockIdx.x >> 5;
    const int b0 = bg * 64;
    const int utile = blockIdx.x & 31;
    const int u0 = utile * 16;

    // ---- permute weights into smem (bf16 fragment layout) ----
    for (int i = tid; i < 16384; i += 256) {
        int c = i & 63, kp = i >> 6, k = kp * 2;
        int gcol = (c >> 4) * 512 + u0 + (c & 15);
        int grp = c >> 3, chunk = k >> 4, kk = k & 15;
        int ln = (c & 7) * 4 + ((kk & 7) >> 1);
        int reg = kk >> 3;
        int off = ((grp * 32 + chunk) * 32 + ln) * 2 + reg;
        {
            __nv_bfloat162 p = __floats2bfloat162_rn(
                Wr[(size_t)k * G4U + gcol], Wr[(size_t)(k + 1) * G4U + gcol]);
            WrS[off] = *(unsigned*)&p;
        }
        if (FUSE) {
            __nv_bfloat162 p = __floats2bfloat162_rn(
                Wk[(size_t)k * G4U + gcol], Wk[(size_t)(k + 1) * G4U + gcol]);
            WkS[off] = *(unsigned*)&p;
        }
    }
    // ---- zero my 1/32 of both h-image buffers ----
    {
        uint4* p0 = (uint4*)&g_himg[bg][0][0];
        uint4* p1 = (uint4*)&g_himg[bg][1][0];
        int base = utile * 128;
        if (tid < 128) {
            p0[base + tid] = make_uint4(0, 0, 0, 0);
            p1[base + tid] = make_uint4(0, 0, 0, 0);
        }
    }

    unsigned* ctr = &g_bar2[pass_id * 4 + bg];
    unsigned nb = 0;
    bar32(ctr, (++nb) * 32);

    float cst[4] = {0.f, 0.f, 0.f, 0.f};
    const float* Etab = sel_dec ? g_Edec : g_Eenc;
    const float* Cb = sel_dec ? g_Cz : g_CbEnc;

    constexpr int TMAX = FUSE ? 129 : 128;
    for (int t = 0; t < TMAX; t++) {
        const bool doR = (t < 128);
        const bool doK = FUSE && (t > 0);
        const __nv_bfloat16* img = &g_himg[bg][t & 1][0];

        // issue 4 quarter cp.async groups (16KB each)
#pragma unroll
        for (int q = 0; q < 4; q++) {
#pragma unroll
            for (int j = 0; j < 4; j++) {
                int idx = tid + j * 256;           // 0..1023
                int strip = idx >> 8, wi = idx & 255;
                int chunk = q * 8 + (wi >> 5), ln = wi & 31;
                int off16 = (strip * 32 + chunk) * 32 + ln;
                cpa16((char*)Asm + (size_t)off16 * 16,
                      (const char*)img + (size_t)off16 * 16);
            }
            asm volatile("cp.async.commit_group;");
        }

        float accR[4][4], accK[4][4];
#pragma unroll
        for (int g = 0; g < 4; g++)
#pragma unroll
            for (int q = 0; q < 4; q++) { accR[g][q] = 0.f; accK[g][q] = 0.f; }

#pragma unroll
        for (int q = 0; q < 4; q++) {
            if (q == 0) asm volatile("cp.async.wait_group 3;" ::: "memory");
            else if (q == 1) asm volatile("cp.async.wait_group 2;" ::: "memory");
            else if (q == 2) asm volatile("cp.async.wait_group 1;" ::: "memory");
            else asm volatile("cp.async.wait_group 0;" ::: "memory");
            __syncthreads();
#pragma unroll
            for (int ch = 0; ch < 8; ch++) {
                int chunk = q * 8 + ch;
                uint4 af = *(const uint4*)(Asm + ((wm * 32 + chunk) * 32 + lane) * 4);
                if (doR) {
#pragma unroll
                    for (int g = 0; g < 4; g++) {
                        uint2 bf = *(const uint2*)(WrS + (((wn * 4 + g) * 32 + chunk) * 32 + lane) * 2);
                        mma16(accR[g], af, bf);
                    }
                }
                if (doK) {
#pragma unroll
                    for (int g = 0; g < 4; g++) {
                        uint2 bf = *(const uint2*)(WkS + (((wn * 4 + g) * 32 + chunk) * 32 + lane) * 2);
                        mma16(accK[g], af, bf);
                    }
                }
            }
        }

        // ---- fused pre write (projection of h_{t-1} for next layer) ----
        if (doK) {
            int row0 = wm * 16 + (lane >> 2);
#pragma unroll
            for (int g = 0; g < 4; g++) {
                int c = wn * 32 + g * 8 + (lane & 3) * 2;
                int gcol = (c >> 4) * 512 + u0 + (c & 15);
                float bv0 = __ldg(&bnext[gcol]);
                float bv1 = __ldg(&bnext[gcol + 1]);
                size_t o1 = ((size_t)(b0 + row0) * cT + (t - 1)) * G4U + gcol;
                size_t o2 = ((size_t)(b0 + row0 + 8) * cT + (t - 1)) * G4U + gcol;
                *(float2*)&g_pre[o1] = make_float2(accK[g][0] + bv0, accK[g][1] + bv1);
                *(float2*)&g_pre[o2] = make_float2(accK[g][2] + bv0, accK[g][3] + bv1);
            }
        }

        // ---- recurrence epilogue ----
        if (doR) {
            int r0 = wm * 16 + (lane >> 2);
#pragma unroll
            for (int g = 0; g < 4; g++) {
                int c = wn * 32 + g * 8 + (lane & 3) * 2;
                zs[r0 * 65 + c] = accR[g][0];
                zs[r0 * 65 + c + 1] = accR[g][1];
                zs[(r0 + 8) * 65 + c] = accR[g][2];
                zs[(r0 + 8) * 65 + c + 1] = accR[g][3];
            }
            __syncthreads();
            __nv_bfloat16* imgout = &g_himg[bg][(t + 1) & 1][0];
#pragma unroll
            for (int j = 0; j < 4; j++) {
                int idx = tid + j * 256;
                int bl = idx >> 4, ul = idx & 15;
                int b = b0 + bl;
                float zi = zs[bl * 65 + ul];
                float zf = zs[bl * 65 + 16 + ul];
                float zg = zs[bl * 65 + 32 + ul];
                float zo = zs[bl * 65 + 48 + ul];
                if (L0) {
                    int xi = Xidx[b * cT + t];
                    zi += Etab[xi * G4U + u0 + ul]        + Cb[(size_t)b * G4U + u0 + ul];
                    zf += Etab[xi * G4U + 512 + u0 + ul]  + Cb[(size_t)b * G4U + 512 + u0 + ul];
                    zg += Etab[xi * G4U + 1024 + u0 + ul] + Cb[(size_t)b * G4U + 1024 + u0 + ul];
                    zo += Etab[xi * G4U + 1536 + u0 + ul] + Cb[(size_t)b * G4U + 1536 + u0 + ul];
                } else {
                    const float* pp = &g_pre[((size_t)b * cT + t) * G4U];
                    zi += pp[u0 + ul];
                    zf += pp[512 + u0 + ul];
                    zg += pp[1024 + u0 + ul];
                    zo += pp[1536 + u0 + ul];
                }
                float ig = 1.f / (1.f + expf(-zi));
                float fg = 1.f / (1.f + expf(-zf));
                float gv = tanhf(zg);
                float og = 1.f / (1.f + expf(-zo));
                cst[j] = fg * cst[j] + ig * gv;
                float h2 = og * tanhf(cst[j]);
                // publish h in permuted bf16 fragment layout
                int strip = bl >> 4, rr = bl & 15;
                int kt = u0 + ul, chunk = kt >> 4, kk = kt & 15;
                int ln2 = (rr & 7) * 4 + ((kk & 7) >> 1);
                int reg = (rr >> 3) + 2 * (kk >> 3);
                imgout[(((strip * 32 + chunk) * 32 + ln2) * 4 + reg) * 2 + (kk & 1)] =
                    __float2bfloat16(h2);
                if (WRSEQ)
                    g_seq[((size_t)b * cT + t) * cU + u0 + ul] = __float2bfloat16(h2);
            }
            bar32(ctr, (++nb) * 32);
        }
    }

#pragma unroll
    for (int j = 0; j < 4; j++) {
        int idx = tid + j * 256;
        int bl = idx >> 4, ul = idx & 15;
        g_c[(b0 + bl) * cU + u0 + ul] = cst[j];
    }
}

// ----------------------- latent: mean / log_sigma / z ----------------------
__global__ void latz_kernel(const float* __restrict__ Wm, const float* __restrict__ bm,
                            const float* __restrict__ Ws, const float* __restrict__ bs,
                            const float* __restrict__ eps) {
    __shared__ float csh[cU];
    __shared__ float red[NTHR];
    const int b = blockIdx.x, tid = threadIdx.x;
    csh[tid] = g_c[b * cU + tid];
    csh[tid + 256] = g_c[b * cU + tid + 256];
    __syncthreads();
    float term = 0.f;
    if (tid < cLAT) {
        float m = bm[tid], ls = bs[tid];
        for (int u = 0; u < cU; u++) {
            const float cv = csh[u];
            m += cv * Wm[u * cLAT + tid];
            ls += cv * Ws[u * cLAT + tid];
        }
        g_z[b * cLAT + tid] = m + expf(0.5f * ls) * eps[b * cLAT + tid];
        term = 1.f + ls - m * m - expf(ls);
    }
    red[tid] = term;
    __syncthreads();
    for (int s = 128; s > 0; s >>= 1) {
        if (tid < s) red[tid] += red[tid + s];
        __syncthreads();
    }
    if (tid == 0) g_latpart[b] = red[0];
}

// ------------------------------- z projection ------------------------------
__global__ void zproj_kernel(const float* __restrict__ dec_k0) {
    __shared__ float zsh[cLAT];
    const int b = blockIdx.x, tid = threadIdx.x;
    if (tid < cLAT) zsh[tid] = g_z[b * cLAT + tid];
    __syncthreads();
    for (int n = tid; n < G4U; n += NTHR) {
        float acc = g_CbDec[b * G4U + n];
        for (int l = 0; l < cLAT; l++) acc += zsh[l] * dec_k0[l * G4U + n];
        g_Cz[b * G4U + n] = acc;
    }
}

// ----------------------- output logits + masked CE -------------------------
__global__ void ce_kernel(const float* __restrict__ Wo, const float* __restrict__ bo,
                          const int* __restrict__ Y, const int* __restrict__ Lv) {
    __shared__ float hsh[8][cU];
    __shared__ float wred[8];
    const int tid = threadIdx.x, w = tid >> 5, lane = tid & 31;
    const int gw = blockIdx.x * 8 + w;
    float sum = 0.f;
    for (int j = 0; j < 8; j++) {
        const int idx = gw + j * 4096;
        const int b = idx >> 7, t = idx & 127;
        const __nv_bfloat16* hp = &g_seq[((size_t)b * cT + t) * cU];
        for (int i = lane; i < cU; i += 32) hsh[w][i] = __bfloat162float(hp[i]);
        __syncwarp();
        const int v0 = lane;
        const int v1 = 32 + lane;
        const int v1c = (v1 < cV) ? v1 : 0;
        float l0 = bo[v0];
        float l1 = bo[v1c];
        for (int u = 0; u < cU; u++) {
            const float hv = hsh[w][u];
            l0 += hv * Wo[u * cV + v0];
            l1 += hv * Wo[u * cV + v1c];
        }
        if (v1 >= cV) l1 = -1e30f;
        float mx = fmaxf(l0, l1);
        for (int o = 16; o; o >>= 1) mx = fmaxf(mx, __shfl_xor_sync(~0u, mx, o));
        float s = expf(l0 - mx) + ((v1 < cV) ? expf(l1 - mx) : 0.f);
        for (int o = 16; o; o >>= 1) s += __shfl_xor_sync(~0u, s, o);
        const float lse = mx + logf(s);
        const int y = Y[b * cT + t];
        const float ly = __shfl_sync(~0u, (y < 32) ? l0 : l1, y & 31);
        if (lane == 0 && t < Lv[b]) sum += (lse - ly);
        __syncwarp();
    }
    if (lane == 0) wred[w] = sum;
    __syncthreads();
    if (tid == 0) {
        float s = 0.f;
        for (int i = 0; i < 8; i++) s += wred[i];
        g_reconpart[blockIdx.x] = s;
    }
}

// ------------------------------- final reduce ------------------------------
__global__ void finish_kernel(float* __restrict__ out, int out_size) {
    __shared__ float red[NTHR];
    const int tid = threadIdx.x;
    float s = 0.f;
    for (int i = tid; i < 512; i += NTHR) s += g_reconpart[i];
    red[tid] = s;
    __syncthreads();
    for (int st = 128; st > 0; st >>= 1) {
        if (tid < st) red[tid] += red[tid + st];
        __syncthreads();
    }
    const float rsum = red[0];
    __syncthreads();
    float s2 = 0.f;
    for (int i = tid; i < cB; i += NTHR) s2 += g_latpart[i];
    red[tid] = s2;
    __syncthreads();
    for (int st = 128; st > 0; st >>= 1) {
        if (tid < st) red[tid] += red[tid + st];
        __syncthreads();
    }
    if (tid == 0) {
        const float recon = rsum / (float)(cB * cT);
        const float lat = -0.5f * red[0] / (float)(cB * cLAT);
        out[0] = recon + lat;
        if (out_size > 1) out[1] = recon;
        if (out_size > 2) out[2] = lat;
    }
}

// --------------------------------- launch ----------------------------------
extern "C" void kernel_launch(void* const* d_in, const int* in_sizes, int n_in,
                              void* d_out, int out_size) {
    const int* X = (const int*)d_in[0];
    const int* Y = (const int*)d_in[1];
    const float* C = (const float*)d_in[2];
    const int* L = (const int*)d_in[3];
    const float* eps = (const float*)d_in[4];
    const float* emb_enc = (const float*)d_in[5];
    const float* emb_dec = (const float*)d_in[6];
    const float* enc_k0 = (const float*)d_in[7];
    const float* enc_rk0 = (const float*)d_in[8];
    const float* enc_b0 = (const float*)d_in[9];
    const float* enc_k1 = (const float*)d_in[10];
    const float* enc_rk1 = (const float*)d_in[11];
    const float* enc_b1 = (const float*)d_in[12];
    const float* enc_k2 = (const float*)d_in[13];
    const float* enc_rk2 = (const float*)d_in[14];
    const float* enc_b2 = (const float*)d_in[15];
    const float* dec_k0 = (const float*)d_in[16];
    const float* dec_rk0 = (const float*)d_in[17];
    const float* dec_b0 = (const float*)d_in[18];
    const float* dec_k1 = (const float*)d_in[19];
    const float* dec_rk1 = (const float*)d_in[20];
    const float* dec_b1 = (const float*)d_in[21];
    const float* dec_k2 = (const float*)d_in[22];
    const float* dec_rk2 = (const float*)d_in[23];
    const float* dec_b2 = (const float*)d_in[24];
    const float* Wm = (const float*)d_in[25];
    const float* bm = (const float*)d_in[26];
    const float* Ws = (const float*)d_in[27];
    const float* bs = (const float*)d_in[28];
    const float* Wo = (const float*)d_in[29];
    const float* bo = (const float*)d_in[30];

    const int SMF = (16384 * 3) * 4 + 64 * 65 * 4;   // 213,248 B (fused)
    const int SMP = (16384 * 2) * 4 + 64 * 65 * 4;   // 147,712 B (plain)
    cudaFuncSetAttribute((const void*)rec3_kernel<true, true, false>,
                         cudaFuncAttributeMaxDynamicSharedMemorySize, SMF);
    cudaFuncSetAttribute((const void*)rec3_kernel<false, true, false>,
                         cudaFuncAttributeMaxDynamicSharedMemorySize, SMF);
    cudaFuncSetAttribute((const void*)rec3_kernel<false, false, false>,
                         cudaFuncAttributeMaxDynamicSharedMemorySize, SMP);
    cudaFuncSetAttribute((const void*)rec3_kernel<false, false, true>,
                         cudaFuncAttributeMaxDynamicSharedMemorySize, SMP);

    prep_kernel<<<597, NTHR>>>(emb_enc, emb_dec, enc_k0, dec_k0, enc_b0, dec_b0, C);

    // ---- encoder ----
    rec3_kernel<true, true, false><<<NCTA, NTHR, SMF>>>(enc_rk0, enc_k1, enc_b1, X, 0, 0);
    rec3_kernel<false, true, false><<<NCTA, NTHR, SMF>>>(enc_rk1, enc_k2, enc_b2, nullptr, 0, 1);
    rec3_kernel<false, false, false><<<NCTA, NTHR, SMP>>>(enc_rk2, nullptr, nullptr, nullptr, 0, 2);

    // ---- latent ----
    latz_kernel<<<cB, NTHR>>>(Wm, bm, Ws, bs, eps);
    zproj_kernel<<<cB, NTHR>>>(dec_k0);

    // ---- decoder ----
    rec3_kernel<true, true, false><<<NCTA, NTHR, SMF>>>(dec_rk0, dec_k1, dec_b1, X, 1, 3);
    rec3_kernel<false, true, false><<<NCTA, NTHR, SMF>>>(dec_rk1, dec_k2, dec_b2, nullptr, 1, 4);
    rec3_kernel<false, false, true><<<NCTA, NTHR, SMP>>>(dec_rk2, nullptr, nullptr, nullptr, 1, 5);

    // ---- losses ----
    ce_kernel<<<512, NTHR>>>(Wo, bo, Y, L);
    finish_kernel<<<1, NTHR>>>((float*)d_out, out_size);
}

// round 4
// speedup vs baseline: 9.2767x; 1.2117x over previous
#include <cuda_runtime.h>
#include <cuda_bf16.h>
#include <cstdint>
#include <cstddef>

// ---------------------------------------------------------------------------
// CVAE forward, Round 4: bf16 mma, gate-grouped accumulators (no zs),
// coalesced h publication, release/acquire scoped barriers.
// B=256 T=128 U=512 LAT=200 V=42 P=3
// ---------------------------------------------------------------------------

constexpr int cB = 256, cT = 128, cU = 512, cLAT = 200, cV = 42, cP = 3;
constexpr int G4U = 2048;
constexpr int NTHR = 256, NCTA = 128;

// ------------------------------- scratch -----------------------------------
__device__ float g_pre[(size_t)cB * cT * G4U];           // 256 MB
__device__ __nv_bfloat16 g_seq[(size_t)cB * cT * cU];    // dec layer2 out
__device__ __nv_bfloat16 g_himg[4][2][32768];            // per-bgroup h image
__device__ float g_c[cB * cU];
__device__ float g_Eenc[cV * G4U];
__device__ float g_Edec[cV * G4U];
__device__ float g_CbEnc[cB * G4U];
__device__ float g_CbDec[cB * G4U];
__device__ float g_Cz[cB * G4U];
__device__ float g_z[cB * cLAT];
__device__ float g_latpart[cB];
__device__ float g_reconpart[512];
__device__ unsigned g_bar2[24];

// ------------------------------ helpers ------------------------------------
__device__ __forceinline__ void cpa16(void* d, const void* s) {
    unsigned ds = (unsigned)__cvta_generic_to_shared(d);
    asm volatile("cp.async.cg.shared.global [%0], [%1], 16;" :: "r"(ds), "l"(s));
}

__device__ __forceinline__ void mma16(float* c, uint4 a, uint2 b) {
    asm volatile(
        "mma.sync.aligned.m16n8k16.row.col.f32.bf16.bf16.f32 "
        "{%0,%1,%2,%3},{%4,%5,%6,%7},{%8,%9},{%0,%1,%2,%3};"
        : "+f"(c[0]), "+f"(c[1]), "+f"(c[2]), "+f"(c[3])
        : "r"(a.x), "r"(a.y), "r"(a.z), "r"(a.w), "r"(b.x), "r"(b.y));
}

// release/acquire scoped 32-CTA barrier (no membar.gpu)
__device__ __forceinline__ void barrel(unsigned* ctr, unsigned target) {
    __syncthreads();
    if (threadIdx.x == 0) {
        asm volatile("red.release.gpu.global.add.u32 [%0], 1;" :: "l"(ctr) : "memory");
        unsigned v;
        do {
            asm volatile("ld.acquire.gpu.global.u32 %0, [%1];" : "=r"(v) : "l"(ctr) : "memory");
        } while (v < target);
    }
    __syncthreads();
}

// ------------------------------ prep kernel --------------------------------
__global__ void prep_kernel(const float* __restrict__ emb_enc,
                            const float* __restrict__ emb_dec,
                            const float* __restrict__ enc_k0,
                            const float* __restrict__ dec_k0,
                            const float* __restrict__ enc_b0,
                            const float* __restrict__ dec_b0,
                            const float* __restrict__ Cmat) {
    const int bid = blockIdx.x, tid = threadIdx.x;
    if (bid < 42) {
        const int v = bid;
        for (int n = tid; n < G4U; n += NTHR) {
            float acc = 0.f;
            for (int l = 0; l < cLAT; l++)
                acc += emb_enc[v * cLAT + l] * enc_k0[l * G4U + n];
            g_Eenc[v * G4U + n] = acc;
        }
    } else if (bid < 84) {
        const int v = bid - 42;
        for (int n = tid; n < G4U; n += NTHR) {
            float acc = 0.f;
            for (int l = 0; l < cLAT; l++)
                acc += emb_dec[v * cLAT + l] * dec_k0[(cLAT + l) * G4U + n];
            g_Edec[v * G4U + n] = acc;
        }
    } else if (bid < 340) {
        const int b = bid - 84;
        for (int n = tid; n < G4U; n += NTHR) {
            float acc = enc_b0[n];
            for (int p = 0; p < cP; p++)
                acc += Cmat[b * cP + p] * enc_k0[(cLAT + p) * G4U + n];
            g_CbEnc[b * G4U + n] = acc;
        }
    } else if (bid < 596) {
        const int b = bid - 340;
        for (int n = tid; n < G4U; n += NTHR) {
            float acc = dec_b0[n];
            for (int p = 0; p < cP; p++)
                acc += Cmat[b * cP + p] * dec_k0[(2 * cLAT + p) * G4U + n];
            g_CbDec[b * G4U + n] = acc;
        }
    } else {
        if (tid < 24) g_bar2[tid] = 0u;
    }
}

// --------------------------- recurrent kernel ------------------------------
// 128 CTAs = 4 bgroups(64 rows) x 32 utiles(16 units -> 64 gate cols).
// Gate-grouped n-block mapping: warp wn's 4 n-blocks = 4 gates of units
// [u0 + wn*8, u0 + wn*8 + 8) -> gates land in one thread's registers.
template <bool L0, bool FUSE, bool WRSEQ>
__global__ __launch_bounds__(256, 1)
void rec4_kernel(const float* __restrict__ Wr, const float* __restrict__ Wk,
                 const float* __restrict__ bnext, const int* __restrict__ Xidx,
                 int sel_dec, int pass_id) {
    extern __shared__ unsigned sm[];
    unsigned* WrS = sm;                                   // 64KB
    unsigned* WkS = sm + 16384;                           // 64KB if FUSE
    constexpr int AOFF = FUSE ? 32768 : 16384;
    unsigned* Asm = sm + AOFF;                            // 64KB
    __nv_bfloat16* hbuf = (__nv_bfloat16*)(sm + AOFF + 16384);  // 2KB

    const int tid = threadIdx.x, lane = tid & 31, w = tid >> 5;
    const int wm = w & 3, wn = w >> 2;
    const int bg = blockIdx.x >> 5;
    const int b0 = bg * 64;
    const int utile = blockIdx.x & 31;
    const int u0 = utile * 16;

    // ---- permute weights into smem (bf16 fragment layout, gate-grouped) ----
    for (int i = tid; i < 16384; i += 256) {
        int c = i & 63, kp = i >> 6, k = kp * 2;
        int grp = c >> 3, j = c & 7;
        int gcol = (grp & 3) * 512 + u0 + (grp >> 2) * 8 + j;
        int chunk = k >> 4, kk = k & 15;
        int ln = j * 4 + ((kk & 7) >> 1);
        int reg = kk >> 3;
        int off = ((grp * 32 + chunk) * 32 + ln) * 2 + reg;
        {
            __nv_bfloat162 p = __floats2bfloat162_rn(
                Wr[(size_t)k * G4U + gcol], Wr[(size_t)(k + 1) * G4U + gcol]);
            WrS[off] = *(unsigned*)&p;
        }
        if (FUSE) {
            __nv_bfloat162 p = __floats2bfloat162_rn(
                Wk[(size_t)k * G4U + gcol], Wk[(size_t)(k + 1) * G4U + gcol]);
            WkS[off] = *(unsigned*)&p;
        }
    }
    // ---- zero my 1/32 of both h-image buffers ----
    {
        uint4* p0 = (uint4*)&g_himg[bg][0][0];
        uint4* p1 = (uint4*)&g_himg[bg][1][0];
        int base = utile * 128;
        if (tid < 128) {
            p0[base + tid] = make_uint4(0, 0, 0, 0);
            p1[base + tid] = make_uint4(0, 0, 0, 0);
        }
    }

    unsigned* ctr = &g_bar2[pass_id * 4 + bg];
    unsigned nb = 0;
    barrel(ctr, (++nb) * 32);

    const float* Etab = sel_dec ? g_Edec : g_Eenc;
    const float* Cb = sel_dec ? g_Cz : g_CbEnc;

    const int r0 = wm * 16 + (lane >> 2);       // local row base (0..63)
    const int ul0 = wn * 8 + (lane & 3) * 2;    // unit base within 16

    // ---- preload static per-thread adds ----
    float2 cbv[2][4];
    if (L0) {
#pragma unroll
        for (int rr = 0; rr < 2; rr++)
#pragma unroll
            for (int g = 0; g < 4; g++)
                cbv[rr][g] = *(const float2*)&Cb[(size_t)(b0 + r0 + rr * 8) * G4U +
                                                 g * 512 + u0 + ul0];
    }
    float2 bb[4];
    if (FUSE) {
#pragma unroll
        for (int g = 0; g < 4; g++)
            bb[g] = *(const float2*)&bnext[g * 512 + u0 + ul0];
    }

    float cst[4] = {0.f, 0.f, 0.f, 0.f};

    constexpr int TMAX = FUSE ? 129 : 128;
    for (int t = 0; t < TMAX; t++) {
        const bool doR = (t < 128);
        const bool doK = FUSE && (t > 0);
        const __nv_bfloat16* img = &g_himg[bg][t & 1][0];

        // issue 4 quarter cp.async groups (16KB each)
#pragma unroll
        for (int q = 0; q < 4; q++) {
#pragma unroll
            for (int j = 0; j < 4; j++) {
                int idx = tid + j * 256;           // 0..1023
                int strip = idx >> 8, wi = idx & 255;
                int chunk = q * 8 + (wi >> 5), ln = wi & 31;
                int off16 = (strip * 32 + chunk) * 32 + ln;
                cpa16((char*)Asm + (size_t)off16 * 16,
                      (const char*)img + (size_t)off16 * 16);
            }
            asm volatile("cp.async.commit_group;");
        }

        float accR[4][4], accK[4][4];
#pragma unroll
        for (int g = 0; g < 4; g++)
#pragma unroll
            for (int q = 0; q < 4; q++) { accR[g][q] = 0.f; accK[g][q] = 0.f; }

#pragma unroll
        for (int q = 0; q < 4; q++) {
            if (q == 0) asm volatile("cp.async.wait_group 3;" ::: "memory");
            else if (q == 1) asm volatile("cp.async.wait_group 2;" ::: "memory");
            else if (q == 2) asm volatile("cp.async.wait_group 1;" ::: "memory");
            else asm volatile("cp.async.wait_group 0;" ::: "memory");
            __syncthreads();
#pragma unroll
            for (int ch = 0; ch < 8; ch++) {
                int chunk = q * 8 + ch;
                uint4 af = *(const uint4*)(Asm + ((wm * 32 + chunk) * 32 + lane) * 4);
                if (doR) {
#pragma unroll
                    for (int g = 0; g < 4; g++) {
                        uint2 bf = *(const uint2*)(WrS + (((wn * 4 + g) * 32 + chunk) * 32 + lane) * 2);
                        mma16(accR[g], af, bf);
                    }
                }
                if (doK) {
#pragma unroll
                    for (int g = 0; g < 4; g++) {
                        uint2 bf = *(const uint2*)(WkS + (((wn * 4 + g) * 32 + chunk) * 32 + lane) * 2);
                        mma16(accK[g], af, bf);
                    }
                }
            }
        }

        // ---- fused pre write (projection of h_{t-1} for next layer) ----
        if (doK) {
#pragma unroll
            for (int g = 0; g < 4; g++) {
                size_t o1 = ((size_t)(b0 + r0) * cT + (t - 1)) * G4U + g * 512 + u0 + ul0;
                size_t o2 = ((size_t)(b0 + r0 + 8) * cT + (t - 1)) * G4U + g * 512 + u0 + ul0;
                *(float2*)&g_pre[o1] = make_float2(accK[g][0] + bb[g].x, accK[g][1] + bb[g].y);
                *(float2*)&g_pre[o2] = make_float2(accK[g][2] + bb[g].x, accK[g][3] + bb[g].y);
            }
        }

        // ---- recurrence epilogue (gates all in-register) ----
        if (doR) {
#pragma unroll
            for (int rr = 0; rr < 2; rr++) {
                const int row = r0 + rr * 8;
                const int b = b0 + row;
                float2 zadd[4];
                if (L0) {
                    const int xi = Xidx[b * cT + t];
#pragma unroll
                    for (int g = 0; g < 4; g++) {
                        float2 ev = *(const float2*)&Etab[xi * G4U + g * 512 + u0 + ul0];
                        zadd[g] = make_float2(ev.x + cbv[rr][g].x, ev.y + cbv[rr][g].y);
                    }
                } else {
                    const float* pp = &g_pre[((size_t)b * cT + t) * G4U];
#pragma unroll
                    for (int g = 0; g < 4; g++)
                        zadd[g] = *(const float2*)&pp[g * 512 + u0 + ul0];
                }
#pragma unroll
                for (int pq = 0; pq < 2; pq++) {
                    const int q = rr * 2 + pq;
                    float zi = accR[0][q] + (pq ? zadd[0].y : zadd[0].x);
                    float zf = accR[1][q] + (pq ? zadd[1].y : zadd[1].x);
                    float zg = accR[2][q] + (pq ? zadd[2].y : zadd[2].x);
                    float zo = accR[3][q] + (pq ? zadd[3].y : zadd[3].x);
                    float ig = 1.f / (1.f + expf(-zi));
                    float fg = 1.f / (1.f + expf(-zf));
                    float gv = tanhf(zg);
                    float og = 1.f / (1.f + expf(-zo));
                    cst[q] = fg * cst[q] + ig * gv;
                    float h2 = og * tanhf(cst[q]);
                    const int ul = ul0 + pq;
                    const int strip = row >> 4, rr2 = row & 15;
                    const int ln2 = (rr2 & 7) * 4 + ((ul & 7) >> 1);
                    const int reg = (rr2 >> 3) + 2 * (ul >> 3);
                    hbuf[strip * 256 + ln2 * 8 + reg * 2 + (ul & 1)] = __float2bfloat16(h2);
                    if (WRSEQ)
                        g_seq[((size_t)b * cT + t) * cU + u0 + ul] = __float2bfloat16(h2);
                }
            }
            __syncthreads();
            // coalesced publish: 128 x uint4
            if (tid < 128) {
                __nv_bfloat16* imgout = &g_himg[bg][(t + 1) & 1][0];
                int strip = tid >> 5, ln = tid & 31;
                uint4 v = ((const uint4*)hbuf)[strip * 32 + ln];
                ((uint4*)imgout)[(strip * 32 + utile) * 32 + ln] = v;
            }
            barrel(ctr, (++nb) * 32);
        }
    }

    // ---- final cell state ----
#pragma unroll
    for (int rr = 0; rr < 2; rr++)
#pragma unroll
        for (int pq = 0; pq < 2; pq++)
            g_c[(size_t)(b0 + r0 + rr * 8) * cU + u0 + ul0 + pq] = cst[rr * 2 + pq];
}

// ----------------------- latent: mean / log_sigma / z ----------------------
__global__ void latz_kernel(const float* __restrict__ Wm, const float* __restrict__ bm,
                            const float* __restrict__ Ws, const float* __restrict__ bs,
                            const float* __restrict__ eps) {
    __shared__ float csh[cU];
    __shared__ float red[NTHR];
    const int b = blockIdx.x, tid = threadIdx.x;
    csh[tid] = g_c[b * cU + tid];
    csh[tid + 256] = g_c[b * cU + tid + 256];
    __syncthreads();
    float term = 0.f;
    if (tid < cLAT) {
        float m = bm[tid], ls = bs[tid];
        for (int u = 0; u < cU; u++) {
            const float cv = csh[u];
            m += cv * Wm[u * cLAT + tid];
            ls += cv * Ws[u * cLAT + tid];
        }
        g_z[b * cLAT + tid] = m + expf(0.5f * ls) * eps[b * cLAT + tid];
        term = 1.f + ls - m * m - expf(ls);
    }
    red[tid] = term;
    __syncthreads();
    for (int s = 128; s > 0; s >>= 1) {
        if (tid < s) red[tid] += red[tid + s];
        __syncthreads();
    }
    if (tid == 0) g_latpart[b] = red[0];
}

// ------------------------------- z projection ------------------------------
__global__ void zproj_kernel(const float* __restrict__ dec_k0) {
    __shared__ float zsh[cLAT];
    const int b = blockIdx.x, tid = threadIdx.x;
    if (tid < cLAT) zsh[tid] = g_z[b * cLAT + tid];
    __syncthreads();
    for (int n = tid; n < G4U; n += NTHR) {
        float acc = g_CbDec[b * G4U + n];
        for (int l = 0; l < cLAT; l++) acc += zsh[l] * dec_k0[l * G4U + n];
        g_Cz[b * G4U + n] = acc;
    }
}

// ----------------------- output logits + masked CE -------------------------
__global__ void ce_kernel(const float* __restrict__ Wo, const float* __restrict__ bo,
                          const int* __restrict__ Y, const int* __restrict__ Lv) {
    __shared__ float hsh[8][cU];
    __shared__ float wred[8];
    const int tid = threadIdx.x, w = tid >> 5, lane = tid & 31;
    const int gw = blockIdx.x * 8 + w;
    float sum = 0.f;
    for (int j = 0; j < 8; j++) {
        const int idx = gw + j * 4096;
        const int b = idx >> 7, t = idx & 127;
        const __nv_bfloat16* hp = &g_seq[((size_t)b * cT + t) * cU];
        for (int i = lane; i < cU; i += 32) hsh[w][i] = __bfloat162float(hp[i]);
        __syncwarp();
        const int v0 = lane;
        const int v1 = 32 + lane;
        const int v1c = (v1 < cV) ? v1 : 0;
        float l0 = bo[v0];
        float l1 = bo[v1c];
        for (int u = 0; u < cU; u++) {
            const float hv = hsh[w][u];
            l0 += hv * Wo[u * cV + v0];
            l1 += hv * Wo[u * cV + v1c];
        }
        if (v1 >= cV) l1 = -1e30f;
        float mx = fmaxf(l0, l1);
        for (int o = 16; o; o >>= 1) mx = fmaxf(mx, __shfl_xor_sync(~0u, mx, o));
        float s = expf(l0 - mx) + ((v1 < cV) ? expf(l1 - mx) : 0.f);
        for (int o = 16; o; o >>= 1) s += __shfl_xor_sync(~0u, s, o);
        const float lse = mx + logf(s);
        const int y = Y[b * cT + t];
        const float ly = __shfl_sync(~0u, (y < 32) ? l0 : l1, y & 31);
        if (lane == 0 && t < Lv[b]) sum += (lse - ly);
        __syncwarp();
    }
    if (lane == 0) wred[w] = sum;
    __syncthreads();
    if (tid == 0) {
        float s = 0.f;
        for (int i = 0; i < 8; i++) s += wred[i];
        g_reconpart[blockIdx.x] = s;
    }
}

// ------------------------------- final reduce ------------------------------
__global__ void finish_kernel(float* __restrict__ out, int out_size) {
    __shared__ float red[NTHR];
    const int tid = threadIdx.x;
    float s = 0.f;
    for (int i = tid; i < 512; i += NTHR) s += g_reconpart[i];
    red[tid] = s;
    __syncthreads();
    for (int st = 128; st > 0; st >>= 1) {
        if (tid < st) red[tid] += red[tid + st];
        __syncthreads();
    }
    const float rsum = red[0];
    __syncthreads();
    float s2 = 0.f;
    for (int i = tid; i < cB; i += NTHR) s2 += g_latpart[i];
    red[tid] = s2;
    __syncthreads();
    for (int st = 128; st > 0; st >>= 1) {
        if (tid < st) red[tid] += red[tid + st];
        __syncthreads();
    }
    if (tid == 0) {
        const float recon = rsum / (float)(cB * cT);
        const float lat = -0.5f * red[0] / (float)(cB * cLAT);
        out[0] = recon + lat;
        if (out_size > 1) out[1] = recon;
        if (out_size > 2) out[2] = lat;
    }
}

// --------------------------------- launch ----------------------------------
extern "C" void kernel_launch(void* const* d_in, const int* in_sizes, int n_in,
                              void* d_out, int out_size) {
    const int* X = (const int*)d_in[0];
    const int* Y = (const int*)d_in[1];
    const float* C = (const float*)d_in[2];
    const int* L = (const int*)d_in[3];
    const float* eps = (const float*)d_in[4];
    const float* emb_enc = (const float*)d_in[5];
    const float* emb_dec = (const float*)d_in[6];
    const float* enc_k0 = (const float*)d_in[7];
    const float* enc_rk0 = (const float*)d_in[8];
    const float* enc_b0 = (const float*)d_in[9];
    const float* enc_k1 = (const float*)d_in[10];
    const float* enc_rk1 = (const float*)d_in[11];
    const float* enc_b1 = (const float*)d_in[12];
    const float* enc_k2 = (const float*)d_in[13];
    const float* enc_rk2 = (const float*)d_in[14];
    const float* enc_b2 = (const float*)d_in[15];
    const float* dec_k0 = (const float*)d_in[16];
    const float* dec_rk0 = (const float*)d_in[17];
    const float* dec_b0 = (const float*)d_in[18];
    const float* dec_k1 = (const float*)d_in[19];
    const float* dec_rk1 = (const float*)d_in[20];
    const float* dec_b1 = (const float*)d_in[21];
    const float* dec_k2 = (const float*)d_in[22];
    const float* dec_rk2 = (const float*)d_in[23];
    const float* dec_b2 = (const float*)d_in[24];
    const float* Wm = (const float*)d_in[25];
    const float* bm = (const float*)d_in[26];
    const float* Ws = (const float*)d_in[27];
    const float* bs = (const float*)d_in[28];
    const float* Wo = (const float*)d_in[29];
    const float* bo = (const float*)d_in[30];

    const int SMF = (16384 * 3 + 512) * 4;   // 198,656 B (fused)
    const int SMP = (16384 * 2 + 512) * 4;   // 133,120 B (plain)
    cudaFuncSetAttribute((const void*)rec4_kernel<true, true, false>,
                         cudaFuncAttributeMaxDynamicSharedMemorySize, SMF);
    cudaFuncSetAttribute((const void*)rec4_kernel<false, true, false>,
                         cudaFuncAttributeMaxDynamicSharedMemorySize, SMF);
    cudaFuncSetAttribute((const void*)rec4_kernel<false, false, false>,
                         cudaFuncAttributeMaxDynamicSharedMemorySize, SMP);
    cudaFuncSetAttribute((const void*)rec4_kernel<false, false, true>,
                         cudaFuncAttributeMaxDynamicSharedMemorySize, SMP);

    prep_kernel<<<597, NTHR>>>(emb_enc, emb_dec, enc_k0, dec_k0, enc_b0, dec_b0, C);

    // ---- encoder ----
    rec4_kernel<true, true, false><<<NCTA, NTHR, SMF>>>(enc_rk0, enc_k1, enc_b1, X, 0, 0);
    rec4_kernel<false, true, false><<<NCTA, NTHR, SMF>>>(enc_rk1, enc_k2, enc_b2, nullptr, 0, 1);
    rec4_kernel<false, false, false><<<NCTA, NTHR, SMP>>>(enc_rk2, nullptr, nullptr, nullptr, 0, 2);

    // ---- latent ----
    latz_kernel<<<cB, NTHR>>>(Wm, bm, Ws, bs, eps);
    zproj_kernel<<<cB, NTHR>>>(dec_k0);

    // ---- decoder ----
    rec4_kernel<true, true, false><<<NCTA, NTHR, SMF>>>(dec_rk0, dec_k1, dec_b1, X, 1, 3);
    rec4_kernel<false, true, false><<<NCTA, NTHR, SMF>>>(dec_rk1, dec_k2, dec_b2, nullptr, 1, 4);
    rec4_kernel<false, false, true><<<NCTA, NTHR, SMP>>>(dec_rk2, nullptr, nullptr, nullptr, 1, 5);

    // ---- losses ----
    ce_kernel<<<512, NTHR>>>(Wo, bo, Y, L);
    finish_kernel<<<1, NTHR>>>((float*)d_out, out_size);
}

// round 5
// speedup vs baseline: 10.7825x; 1.1623x over previous
#include <cuda_runtime.h>
#include <cuda_bf16.h>
#include <cstdint>
#include <cstddef>

// ---------------------------------------------------------------------------
// CVAE forward, Round 5: dataflow flags replace per-step barriers.
// bf16 mma, gate-grouped accumulators, per-utile epoch flags + quarter-wise
// cp.async, prefetched additive terms, MUFU epilogue.
// B=256 T=128 U=512 LAT=200 V=42 P=3
// ---------------------------------------------------------------------------

constexpr int cB = 256, cT = 128, cU = 512, cLAT = 200, cV = 42, cP = 3;
constexpr int G4U = 2048;
constexpr int NTHR = 256, NCTA = 128;

// ------------------------------- scratch -----------------------------------
__device__ float g_pre[(size_t)cB * cT * G4U];           // 256 MB
__device__ __nv_bfloat16 g_seq[(size_t)cB * cT * cU];    // dec layer2 out
__device__ __nv_bfloat16 g_himg[4][2][32768];            // per-bgroup h image
__device__ float g_c[cB * cU];
__device__ float g_Eenc[cV * G4U];
__device__ float g_Edec[cV * G4U];
__device__ float g_CbEnc[cB * G4U];
__device__ float g_CbDec[cB * G4U];
__device__ float g_Cz[cB * G4U];
__device__ float g_z[cB * cLAT];
__device__ float g_latpart[cB];
__device__ float g_reconpart[512];
__device__ unsigned g_bar2[24];
__device__ unsigned g_flag[6 * 4 * 32];                  // per pass/bgroup/utile

// ------------------------------ helpers ------------------------------------
__device__ __forceinline__ void cpa16(void* d, const void* s) {
    unsigned ds = (unsigned)__cvta_generic_to_shared(d);
    asm volatile("cp.async.cg.shared.global [%0], [%1], 16;" :: "r"(ds), "l"(s));
}

__device__ __forceinline__ void mma16(float* c, uint4 a, uint2 b) {
    asm volatile(
        "mma.sync.aligned.m16n8k16.row.col.f32.bf16.bf16.f32 "
        "{%0,%1,%2,%3},{%4,%5,%6,%7},{%8,%9},{%0,%1,%2,%3};"
        : "+f"(c[0]), "+f"(c[1]), "+f"(c[2]), "+f"(c[3])
        : "r"(a.x), "r"(a.y), "r"(a.z), "r"(a.w), "r"(b.x), "r"(b.y));
}

__device__ __forceinline__ float sigf(float x) {
    float r;
    asm("{\n\t.reg .f32 t;\n\t"
        "mul.f32 t, %1, 0fBFB8AA3B;\n\t"
        "ex2.approx.f32 t, t;\n\t"
        "add.f32 t, t, 0f3F800000;\n\t"
        "rcp.approx.f32 %0, t;\n\t}"
        : "=f"(r) : "f"(x));
    return r;
}

__device__ __forceinline__ float tanha(float x) {
    float r;
    asm("tanh.approx.f32 %0, %1;" : "=f"(r) : "f"(x));
    return r;
}

// initial-sync barrier (per pass/bgroup, used once)
__device__ __forceinline__ void barrel(unsigned* ctr, unsigned target) {
    __syncthreads();
    if (threadIdx.x == 0) {
        asm volatile("red.release.gpu.global.add.u32 [%0], 1;" :: "l"(ctr) : "memory");
        unsigned v;
        do {
            asm volatile("ld.acquire.gpu.global.u32 %0, [%1];" : "=r"(v) : "l"(ctr) : "memory");
        } while (v < target);
    }
    __syncthreads();
}

// wait until 8 producer flags (f[0..7]) reach tgt; warp-converged.
__device__ __forceinline__ void waitq(const unsigned* f, unsigned tgt, int lane) {
    unsigned done;
    do {
        unsigned v = tgt;
        if (lane < 8)
            asm volatile("ld.acquire.gpu.global.u32 %0, [%1];"
                         : "=r"(v) : "l"(f + lane) : "memory");
        done = __ballot_sync(0xffffffffu, v >= tgt);
    } while (done != 0xffffffffu);
}

// ------------------------------ prep kernel --------------------------------
__global__ void prep_kernel(const float* __restrict__ emb_enc,
                            const float* __restrict__ emb_dec,
                            const float* __restrict__ enc_k0,
                            const float* __restrict__ dec_k0,
                            const float* __restrict__ enc_b0,
                            const float* __restrict__ dec_b0,
                            const float* __restrict__ Cmat) {
    const int bid = blockIdx.x, tid = threadIdx.x;
    if (bid < 42) {
        const int v = bid;
        for (int n = tid; n < G4U; n += NTHR) {
            float acc = 0.f;
            for (int l = 0; l < cLAT; l++)
                acc += emb_enc[v * cLAT + l] * enc_k0[l * G4U + n];
            g_Eenc[v * G4U + n] = acc;
        }
    } else if (bid < 84) {
        const int v = bid - 42;
        for (int n = tid; n < G4U; n += NTHR) {
            float acc = 0.f;
            for (int l = 0; l < cLAT; l++)
                acc += emb_dec[v * cLAT + l] * dec_k0[(cLAT + l) * G4U + n];
            g_Edec[v * G4U + n] = acc;
        }
    } else if (bid < 340) {
        const int b = bid - 84;
        for (int n = tid; n < G4U; n += NTHR) {
            float acc = enc_b0[n];
            for (int p = 0; p < cP; p++)
                acc += Cmat[b * cP + p] * enc_k0[(cLAT + p) * G4U + n];
            g_CbEnc[b * G4U + n] = acc;
        }
    } else if (bid < 596) {
        const int b = bid - 340;
        for (int n = tid; n < G4U; n += NTHR) {
            float acc = dec_b0[n];
            for (int p = 0; p < cP; p++)
                acc += Cmat[b * cP + p] * dec_k0[(2 * cLAT + p) * G4U + n];
            g_CbDec[b * G4U + n] = acc;
        }
    } else {
        for (int i = tid; i < 6 * 4 * 32; i += NTHR) g_flag[i] = 0u;
        if (tid < 24) g_bar2[tid] = 0u;
    }
}

// --------------------------- recurrent kernel ------------------------------
// 128 CTAs = 4 bgroups(64 rows) x 32 utiles(16 units -> 64 gate cols).
template <bool L0, bool FUSE, bool WRSEQ>
__global__ __launch_bounds__(256, 1)
void rec5_kernel(const float* __restrict__ Wr, const float* __restrict__ Wk,
                 const float* __restrict__ bnext, const int* __restrict__ Xidx,
                 int sel_dec, int pass_id) {
    extern __shared__ unsigned sm[];
    unsigned* WrS = sm;                                   // 64KB
    unsigned* WkS = sm + 16384;                           // 64KB if FUSE
    constexpr int AOFF = FUSE ? 32768 : 16384;
    unsigned* Asm = sm + AOFF;                            // 64KB
    __nv_bfloat16* hbuf = (__nv_bfloat16*)(sm + AOFF + 16384);  // 2KB

    const int tid = threadIdx.x, lane = tid & 31, w = tid >> 5;
    const int wm = w & 3, wn = w >> 2;
    const int bg = blockIdx.x >> 5;
    const int b0 = bg * 64;
    const int utile = blockIdx.x & 31;
    const int u0 = utile * 16;

    // ---- permute weights into smem (bf16 fragment layout, gate-grouped) ----
    for (int i = tid; i < 16384; i += 256) {
        int c = i & 63, kp = i >> 6, k = kp * 2;
        int grp = c >> 3, j = c & 7;
        int gcol = (grp & 3) * 512 + u0 + (grp >> 2) * 8 + j;
        int chunk = k >> 4, kk = k & 15;
        int ln = j * 4 + ((kk & 7) >> 1);
        int reg = kk >> 3;
        int off = ((grp * 32 + chunk) * 32 + ln) * 2 + reg;
        {
            __nv_bfloat162 p = __floats2bfloat162_rn(
                Wr[(size_t)k * G4U + gcol], Wr[(size_t)(k + 1) * G4U + gcol]);
            WrS[off] = *(unsigned*)&p;
        }
        if (FUSE) {
            __nv_bfloat162 p = __floats2bfloat162_rn(
                Wk[(size_t)k * G4U + gcol], Wk[(size_t)(k + 1) * G4U + gcol]);
            WkS[off] = *(unsigned*)&p;
        }
    }
    // ---- zero my 1/32 of both h-image buffers ----
    {
        uint4* p0 = (uint4*)&g_himg[bg][0][0];
        uint4* p1 = (uint4*)&g_himg[bg][1][0];
        int base = utile * 128;
        if (tid < 128) {
            p0[base + tid] = make_uint4(0, 0, 0, 0);
            p1[base + tid] = make_uint4(0, 0, 0, 0);
        }
    }
    barrel(&g_bar2[pass_id * 4 + bg], 32);   // zero-images visible

    const float* Etab = sel_dec ? g_Edec : g_Eenc;
    const float* Cb = sel_dec ? g_Cz : g_CbEnc;
    const unsigned* flg = &g_flag[(pass_id * 4 + bg) * 32];
    unsigned* myflag = &g_flag[(pass_id * 4 + bg) * 32 + utile];

    const int r0 = wm * 16 + (lane >> 2);       // local row base (0..63)
    const int ul0 = wn * 8 + (lane & 3) * 2;    // unit base within 16

    // ---- preload static per-thread adds ----
    float2 cbv[2][4];
    if (L0) {
#pragma unroll
        for (int rr = 0; rr < 2; rr++)
#pragma unroll
            for (int g = 0; g < 4; g++)
                cbv[rr][g] = *(const float2*)&Cb[(size_t)(b0 + r0 + rr * 8) * G4U +
                                                 g * 512 + u0 + ul0];
    }
    float2 bb[4];
    if (FUSE) {
#pragma unroll
        for (int g = 0; g < 4; g++)
            bb[g] = *(const float2*)&bnext[g * 512 + u0 + ul0];
    }

    float cst[4] = {0.f, 0.f, 0.f, 0.f};

    constexpr int TMAX = FUSE ? 129 : 128;
    for (int t = 0; t < TMAX; t++) {
        const bool doR = (t < 128);
        const bool doK = FUSE && (t > 0);
        const __nv_bfloat16* img = &g_himg[bg][t & 1][0];

        // poll producers per quarter, then issue that quarter's cp.async
#pragma unroll
        for (int q = 0; q < 4; q++) {
            if (t > 0) waitq(flg + q * 8, (unsigned)t, lane);
#pragma unroll
            for (int j = 0; j < 4; j++) {
                int idx = tid + j * 256;           // 0..1023
                int strip = idx >> 8, wi = idx & 255;
                int chunk = q * 8 + (wi >> 5), ln = wi & 31;
                int off16 = (strip * 32 + chunk) * 32 + ln;
                cpa16((char*)Asm + (size_t)off16 * 16,
                      (const char*)img + (size_t)off16 * 16);
            }
            asm volatile("cp.async.commit_group;");
        }

        // ---- prefetch additive terms (off critical path) ----
        float2 zadd[2][4];
        if (doR) {
            if (L0) {
                int xi0 = Xidx[(b0 + r0) * cT + t];
                int xi1 = Xidx[(b0 + r0 + 8) * cT + t];
#pragma unroll
                for (int g = 0; g < 4; g++) {
                    float2 e0 = *(const float2*)&Etab[xi0 * G4U + g * 512 + u0 + ul0];
                    float2 e1 = *(const float2*)&Etab[xi1 * G4U + g * 512 + u0 + ul0];
                    zadd[0][g] = make_float2(e0.x + cbv[0][g].x, e0.y + cbv[0][g].y);
                    zadd[1][g] = make_float2(e1.x + cbv[1][g].x, e1.y + cbv[1][g].y);
                }
            } else {
#pragma unroll
                for (int rr = 0; rr < 2; rr++)
#pragma unroll
                    for (int g = 0; g < 4; g++)
                        zadd[rr][g] = __ldcs((const float2*)&g_pre[
                            ((size_t)(b0 + r0 + rr * 8) * cT + t) * G4U +
                            g * 512 + u0 + ul0]);
            }
        }

        float accR[4][4], accK[4][4];
#pragma unroll
        for (int g = 0; g < 4; g++)
#pragma unroll
            for (int q = 0; q < 4; q++) { accR[g][q] = 0.f; accK[g][q] = 0.f; }

#pragma unroll
        for (int q = 0; q < 4; q++) {
            if (q == 0) asm volatile("cp.async.wait_group 3;" ::: "memory");
            else if (q == 1) asm volatile("cp.async.wait_group 2;" ::: "memory");
            else if (q == 2) asm volatile("cp.async.wait_group 1;" ::: "memory");
            else asm volatile("cp.async.wait_group 0;" ::: "memory");
            __syncthreads();
#pragma unroll
            for (int ch = 0; ch < 8; ch++) {
                int chunk = q * 8 + ch;
                uint4 af = *(const uint4*)(Asm + ((wm * 32 + chunk) * 32 + lane) * 4);
                if (doR) {
#pragma unroll
                    for (int g = 0; g < 4; g++) {
                        uint2 bf = *(const uint2*)(WrS + (((wn * 4 + g) * 32 + chunk) * 32 + lane) * 2);
                        mma16(accR[g], af, bf);
                    }
                }
                if (doK) {
#pragma unroll
                    for (int g = 0; g < 4; g++) {
                        uint2 bf = *(const uint2*)(WkS + (((wn * 4 + g) * 32 + chunk) * 32 + lane) * 2);
                        mma16(accK[g], af, bf);
                    }
                }
            }
        }

        // ---- fused pre write (projection of h_{t-1} for next layer) ----
        if (doK) {
#pragma unroll
            for (int g = 0; g < 4; g++) {
                size_t o1 = ((size_t)(b0 + r0) * cT + (t - 1)) * G4U + g * 512 + u0 + ul0;
                size_t o2 = ((size_t)(b0 + r0 + 8) * cT + (t - 1)) * G4U + g * 512 + u0 + ul0;
                __stcs((float2*)&g_pre[o1],
                       make_float2(accK[g][0] + bb[g].x, accK[g][1] + bb[g].y));
                __stcs((float2*)&g_pre[o2],
                       make_float2(accK[g][2] + bb[g].x, accK[g][3] + bb[g].y));
            }
        }

        // ---- recurrence epilogue (gates in-register, MUFU math) ----
        if (doR) {
#pragma unroll
            for (int rr = 0; rr < 2; rr++) {
                const int row = r0 + rr * 8;
                const int b = b0 + row;
#pragma unroll
                for (int pq = 0; pq < 2; pq++) {
                    const int q = rr * 2 + pq;
                    float zi = accR[0][q] + (pq ? zadd[rr][0].y : zadd[rr][0].x);
                    float zf = accR[1][q] + (pq ? zadd[rr][1].y : zadd[rr][1].x);
                    float zg = accR[2][q] + (pq ? zadd[rr][2].y : zadd[rr][2].x);
                    float zo = accR[3][q] + (pq ? zadd[rr][3].y : zadd[rr][3].x);
                    float ig = sigf(zi);
                    float fg = sigf(zf);
                    float gv = tanhf(zg);
                    float og = sigf(zo);
                    cst[q] = fg * cst[q] + ig * gv;
                    float h2 = og * tanha(cst[q]);
                    const int ul = ul0 + pq;
                    const int strip = row >> 4, rr2 = row & 15;
                    const int ln2 = (rr2 & 7) * 4 + ((ul & 7) >> 1);
                    const int reg = (rr2 >> 3) + 2 * (ul >> 3);
                    hbuf[strip * 256 + ln2 * 8 + reg * 2 + (ul & 1)] = __float2bfloat16(h2);
                    if (WRSEQ)
                        g_seq[((size_t)b * cT + t) * cU + u0 + ul] = __float2bfloat16(h2);
                }
            }
            __syncthreads();
            // coalesced publish: 128 x uint4
            if (tid < 128) {
                __nv_bfloat16* imgout = &g_himg[bg][(t + 1) & 1][0];
                int strip = tid >> 5, ln = tid & 31;
                uint4 v = ((const uint4*)hbuf)[strip * 32 + ln];
                ((uint4*)imgout)[(strip * 32 + utile) * 32 + ln] = v;
            }
            __syncthreads();
            if (tid == 0)
                asm volatile("red.release.gpu.global.add.u32 [%0], 1;"
                             :: "l"(myflag) : "memory");
        }
    }

    // ---- final cell state ----
#pragma unroll
    for (int rr = 0; rr < 2; rr++)
#pragma unroll
        for (int pq = 0; pq < 2; pq++)
            g_c[(size_t)(b0 + r0 + rr * 8) * cU + u0 + ul0 + pq] = cst[rr * 2 + pq];
}

// ----------------------- latent: mean / log_sigma / z ----------------------
__global__ void latz_kernel(const float* __restrict__ Wm, const float* __restrict__ bm,
                            const float* __restrict__ Ws, const float* __restrict__ bs,
                            const float* __restrict__ eps) {
    __shared__ float csh[cU];
    __shared__ float red[NTHR];
    const int b = blockIdx.x, tid = threadIdx.x;
    csh[tid] = g_c[b * cU + tid];
    csh[tid + 256] = g_c[b * cU + tid + 256];
    __syncthreads();
    float term = 0.f;
    if (tid < cLAT) {
        float m = bm[tid], ls = bs[tid];
        for (int u = 0; u < cU; u++) {
            const float cv = csh[u];
            m += cv * Wm[u * cLAT + tid];
            ls += cv * Ws[u * cLAT + tid];
        }
        g_z[b * cLAT + tid] = m + expf(0.5f * ls) * eps[b * cLAT + tid];
        term = 1.f + ls - m * m - expf(ls);
    }
    red[tid] = term;
    __syncthreads();
    for (int s = 128; s > 0; s >>= 1) {
        if (tid < s) red[tid] += red[tid + s];
        __syncthreads();
    }
    if (tid == 0) g_latpart[b] = red[0];
}

// ------------------------------- z projection ------------------------------
__global__ void zproj_kernel(const float* __restrict__ dec_k0) {
    __shared__ float zsh[cLAT];
    const int b = blockIdx.x, tid = threadIdx.x;
    if (tid < cLAT) zsh[tid] = g_z[b * cLAT + tid];
    __syncthreads();
    for (int n = tid; n < G4U; n += NTHR) {
        float acc = g_CbDec[b * G4U + n];
        for (int l = 0; l < cLAT; l++) acc += zsh[l] * dec_k0[l * G4U + n];
        g_Cz[b * G4U + n] = acc;
    }
}

// ----------------------- output logits + masked CE -------------------------
__global__ void ce_kernel(const float* __restrict__ Wo, const float* __restrict__ bo,
                          const int* __restrict__ Y, const int* __restrict__ Lv) {
    __shared__ float hsh[8][cU];
    __shared__ float wred[8];
    const int tid = threadIdx.x, w = tid >> 5, lane = tid & 31;
    const int gw = blockIdx.x * 8 + w;
    float sum = 0.f;
    for (int j = 0; j < 8; j++) {
        const int idx = gw + j * 4096;
        const int b = idx >> 7, t = idx & 127;
        const __nv_bfloat16* hp = &g_seq[((size_t)b * cT + t) * cU];
        for (int i = lane; i < cU; i += 32) hsh[w][i] = __bfloat162float(hp[i]);
        __syncwarp();
        const int v0 = lane;
        const int v1 = 32 + lane;
        const int v1c = (v1 < cV) ? v1 : 0;
        float l0 = bo[v0];
        float l1 = bo[v1c];
        for (int u = 0; u < cU; u++) {
            const float hv = hsh[w][u];
            l0 += hv * Wo[u * cV + v0];
            l1 += hv * Wo[u * cV + v1c];
        }
        if (v1 >= cV) l1 = -1e30f;
        float mx = fmaxf(l0, l1);
        for (int o = 16; o; o >>= 1) mx = fmaxf(mx, __shfl_xor_sync(~0u, mx, o));
        float s = expf(l0 - mx) + ((v1 < cV) ? expf(l1 - mx) : 0.f);
        for (int o = 16; o; o >>= 1) s += __shfl_xor_sync(~0u, s, o);
        const float lse = mx + logf(s);
        const int y = Y[b * cT + t];
        const float ly = __shfl_sync(~0u, (y < 32) ? l0 : l1, y & 31);
        if (lane == 0 && t < Lv[b]) sum += (lse - ly);
        __syncwarp();
    }
    if (lane == 0) wred[w] = sum;
    __syncthreads();
    if (tid == 0) {
        float s = 0.f;
        for (int i = 0; i < 8; i++) s += wred[i];
        g_reconpart[blockIdx.x] = s;
    }
}

// ------------------------------- final reduce ------------------------------
__global__ void finish_kernel(float* __restrict__ out, int out_size) {
    __shared__ float red[NTHR];
    const int tid = threadIdx.x;
    float s = 0.f;
    for (int i = tid; i < 512; i += NTHR) s += g_reconpart[i];
    red[tid] = s;
    __syncthreads();
    for (int st = 128; st > 0; st >>= 1) {
        if (tid < st) red[tid] += red[tid + st];
        __syncthreads();
    }
    const float rsum = red[0];
    __syncthreads();
    float s2 = 0.f;
    for (int i = tid; i < cB; i += NTHR) s2 += g_latpart[i];
    red[tid] = s2;
    __syncthreads();
    for (int st = 128; st > 0; st >>= 1) {
        if (tid < st) red[tid] += red[tid + st];
        __syncthreads();
    }
    if (tid == 0) {
        const float recon = rsum / (float)(cB * cT);
        const float lat = -0.5f * red[0] / (float)(cB * cLAT);
        out[0] = recon + lat;
        if (out_size > 1) out[1] = recon;
        if (out_size > 2) out[2] = lat;
    }
}

// --------------------------------- launch ----------------------------------
extern "C" void kernel_launch(void* const* d_in, const int* in_sizes, int n_in,
                              void* d_out, int out_size) {
    const int* X = (const int*)d_in[0];
    const int* Y = (const int*)d_in[1];
    const float* C = (const float*)d_in[2];
    const int* L = (const int*)d_in[3];
    const float* eps = (const float*)d_in[4];
    const float* emb_enc = (const float*)d_in[5];
    const float* emb_dec = (const float*)d_in[6];
    const float* enc_k0 = (const float*)d_in[7];
    const float* enc_rk0 = (const float*)d_in[8];
    const float* enc_b0 = (const float*)d_in[9];
    const float* enc_k1 = (const float*)d_in[10];
    const float* enc_rk1 = (const float*)d_in[11];
    const float* enc_b1 = (const float*)d_in[12];
    const float* enc_k2 = (const float*)d_in[13];
    const float* enc_rk2 = (const float*)d_in[14];
    const float* enc_b2 = (const float*)d_in[15];
    const float* dec_k0 = (const float*)d_in[16];
    const float* dec_rk0 = (const float*)d_in[17];
    const float* dec_b0 = (const float*)d_in[18];
    const float* dec_k1 = (const float*)d_in[19];
    const float* dec_rk1 = (const float*)d_in[20];
    const float* dec_b1 = (const float*)d_in[21];
    const float* dec_k2 = (const float*)d_in[22];
    const float* dec_rk2 = (const float*)d_in[23];
    const float* dec_b2 = (const float*)d_in[24];
    const float* Wm = (const float*)d_in[25];
    const float* bm = (const float*)d_in[26];
    const float* Ws = (const float*)d_in[27];
    const float* bs = (const float*)d_in[28];
    const float* Wo = (const float*)d_in[29];
    const float* bo = (const float*)d_in[30];

    const int SMF = (16384 * 3 + 512) * 4;   // 198,656 B (fused)
    const int SMP = (16384 * 2 + 512) * 4;   // 133,120 B (plain)
    cudaFuncSetAttribute((const void*)rec5_kernel<true, true, false>,
                         cudaFuncAttributeMaxDynamicSharedMemorySize, SMF);
    cudaFuncSetAttribute((const void*)rec5_kernel<false, true, false>,
                         cudaFuncAttributeMaxDynamicSharedMemorySize, SMF);
    cudaFuncSetAttribute((const void*)rec5_kernel<false, false, false>,
                         cudaFuncAttributeMaxDynamicSharedMemorySize, SMP);
    cudaFuncSetAttribute((const void*)rec5_kernel<false, false, true>,
                         cudaFuncAttributeMaxDynamicSharedMemorySize, SMP);

    prep_kernel<<<597, NTHR>>>(emb_enc, emb_dec, enc_k0, dec_k0, enc_b0, dec_b0, C);

    // ---- encoder ----
    rec5_kernel<true, true, false><<<NCTA, NTHR, SMF>>>(enc_rk0, enc_k1, enc_b1, X, 0, 0);
    rec5_kernel<false, true, false><<<NCTA, NTHR, SMF>>>(enc_rk1, enc_k2, enc_b2, nullptr, 0, 1);
    rec5_kernel<false, false, false><<<NCTA, NTHR, SMP>>>(enc_rk2, nullptr, nullptr, nullptr, 0, 2);

    // ---- latent ----
    latz_kernel<<<cB, NTHR>>>(Wm, bm, Ws, bs, eps);
    zproj_kernel<<<cB, NTHR>>>(dec_k0);

    // ---- decoder ----
    rec5_kernel<true, true, false><<<NCTA, NTHR, SMF>>>(dec_rk0, dec_k1, dec_b1, X, 1, 3);
    rec5_kernel<false, true, false><<<NCTA, NTHR, SMF>>>(dec_rk1, dec_k2, dec_b2, nullptr, 1, 4);
    rec5_kernel<false, false, true><<<NCTA, NTHR, SMP>>>(dec_rk2, nullptr, nullptr, nullptr, 1, 5);

    // ---- losses ----
    ce_kernel<<<512, NTHR>>>(Wo, bo, Y, L);
    finish_kernel<<<1, NTHR>>>((float*)d_out, out_size);
}